// round 8
// baseline (speedup 1.0000x reference)
#include <cuda_runtime.h>
#include <math.h>
#include <stdint.h>

#define BDIM 2
#define SEQ  2048
#define DMODEL 1024
#define NH   16
#define HD   64
#define MROWS (BDIM*SEQ)     // 4096
#define DFF  4096
#define LN_EPS 1e-9f

// ---------------- scratch ----------------
__device__ float g_buf0[(size_t)MROWS*DMODEL];  // ln1 out, then attention O
__device__ float g_buf1[(size_t)MROWS*DMODEL];  // Q, then ln2 out
__device__ float g_buf2[(size_t)MROWS*DMODEL];  // K
__device__ float g_buf3[(size_t)MROWS*DMODEL];  // V
__device__ float g_buf4[(size_t)MROWS*DMODEL];  // y1 = x + attn
__device__ float g_mid [(size_t)MROWS*DFF];     // MLP mid (gelu, rounded)
// tf32-rounded weights
__device__ float g_wq[(size_t)DMODEL*DMODEL];
__device__ float g_wk[(size_t)DMODEL*DMODEL];
__device__ float g_wv[(size_t)DMODEL*DMODEL];
__device__ float g_wo[(size_t)DMODEL*DMODEL];
__device__ float g_wup[(size_t)DFF*DMODEL];
__device__ float g_wdn[(size_t)DMODEL*DFF];

// ---------------- helpers ----------------
__device__ __forceinline__ uint32_t f2tf32(float x) {
    uint32_t u; asm("cvt.rna.tf32.f32 %0, %1;" : "=r"(u) : "f"(x));
    return u;
}
__device__ __forceinline__ float rtf(float x) { return __uint_as_float(f2tf32(x)); }

__device__ __forceinline__ void cp16(void* s, const void* g) {
    uint32_t sa = (uint32_t)__cvta_generic_to_shared(s);
    asm volatile("cp.async.cg.shared.global [%0], [%1], 16;" :: "r"(sa), "l"(g));
}
__device__ __forceinline__ void cp_commit() {
    asm volatile("cp.async.commit_group;");
}
template<int NGRP> __device__ __forceinline__ void cp_wait() {
    asm volatile("cp.async.wait_group %0;" :: "n"(NGRP));
}
__device__ __forceinline__ float gelu_exact(float v) {
    return 0.5f * v * (1.0f + erff(v * 0.7071067811865476f));
}
__device__ __forceinline__ void mma_tf32(
    float& c0, float& c1, float& c2, float& c3,
    uint32_t a0, uint32_t a1, uint32_t a2, uint32_t a3,
    uint32_t b0, uint32_t b1)
{
    asm volatile(
        "mma.sync.aligned.m16n8k8.row.col.f32.tf32.tf32.f32 "
        "{%0,%1,%2,%3}, {%4,%5,%6,%7}, {%8,%9}, {%0,%1,%2,%3};"
        : "+f"(c0), "+f"(c1), "+f"(c2), "+f"(c3)
        : "r"(a0), "r"(a1), "r"(a2), "r"(a3), "r"(b0), "r"(b1));
}

// ---------------- weight rounding ----------------
__global__ __launch_bounds__(256) void round_kernel(const float* __restrict__ in,
                                                    float* __restrict__ out, int n4) {
    int i = blockIdx.x * blockDim.x + threadIdx.x;
    if (i < n4) {
        float4 v = ((const float4*)in)[i];
        v.x = rtf(v.x); v.y = rtf(v.y); v.z = rtf(v.z); v.w = rtf(v.w);
        ((float4*)out)[i] = v;
    }
}

// ---------------- LayerNorm (ddof=1), output rounded to tf32 ----------------
__global__ __launch_bounds__(256) void ln_kernel(
    const float* __restrict__ x, const float* __restrict__ mean_scale,
    const float* __restrict__ std_scale, float* __restrict__ out)
{
    int row = blockIdx.x;
    int t = threadIdx.x;
    const float4* xr = (const float4*)(x + (size_t)row*DMODEL);
    float4 v = xr[t];

    __shared__ float red[8];
    float s = v.x + v.y + v.z + v.w;
    #pragma unroll
    for (int m = 16; m > 0; m >>= 1) s += __shfl_xor_sync(0xffffffffu, s, m);
    if ((t & 31) == 0) red[t >> 5] = s;
    __syncthreads();
    if (t < 8) {
        float r = red[t];
        #pragma unroll
        for (int m = 4; m > 0; m >>= 1) r += __shfl_xor_sync(0xffu, r, m);
        if (t == 0) red[0] = r;
    }
    __syncthreads();
    float mean = red[0] * (1.0f / DMODEL);
    float dx = v.x - mean, dy = v.y - mean, dz = v.z - mean, dw = v.w - mean;
    float q = dx*dx + dy*dy + dz*dz + dw*dw;
    __syncthreads();
    #pragma unroll
    for (int m = 16; m > 0; m >>= 1) q += __shfl_xor_sync(0xffffffffu, q, m);
    if ((t & 31) == 0) red[t >> 5] = q;
    __syncthreads();
    if (t < 8) {
        float r = red[t];
        #pragma unroll
        for (int m = 4; m > 0; m >>= 1) r += __shfl_xor_sync(0xffu, r, m);
        if (t == 0) red[0] = r;
    }
    __syncthreads();
    float var = red[0] * (1.0f / (DMODEL - 1));
    float rstd = rsqrtf(var + LN_EPS);

    float4 msv = ((const float4*)mean_scale)[t];
    float4 ssv = ((const float4*)std_scale)[t];
    float4 o;
    o.x = rtf(dx * rstd * ssv.x + msv.x);
    o.y = rtf(dy * rstd * ssv.y + msv.y);
    o.z = rtf(dz * rstd * ssv.z + msv.z);
    o.w = rtf(dw * rstd * ssv.w + msv.w);
    ((float4*)(out + (size_t)row*DMODEL))[t] = o;
}

// ---------------- TF32 mma.sync GEMM, mma-native smem layout, 3-stage ----------------
// C[m,n] = sum_k A[m,k]*W[n,k] (+ epilogue). A, W tf32-pre-rounded.
// Tile 128x128x32. smem per stage: A 4096 + B 4096 floats.
// Layout per 32-K chunk: float offset(m,k) = (k>>3)*1024 + (((k>>2)&1))*512 + m*4 + (k&3).
//  -> cp.async 16B chunks contiguous; fragment LDS bank = (g*4+q) -> conflict-free.
#define EPI_RND  0
#define EPI_GELU 1
#define EPI_ADD  2

#define STG_FLOATS 8192                    // per stage (A+B)
#define G6_SMEM (3 * STG_FLOATS * 4)       // 98304 B

__device__ __forceinline__ void g6_fill(
    const float* __restrict__ Ag, const float* __restrict__ Wg, int K, int k0,
    float* __restrict__ As, float* __restrict__ Bs, int t)
{
    #pragma unroll
    for (int i = 0; i < 4; i++) {
        int chunk = t + i * 256;              // 0..1023
        int m = chunk >> 3, kc = chunk & 7;
        int off = ((kc >> 1) << 10) + ((kc & 1) << 9) + (m << 2);
        const size_t gofs = (size_t)m * K + k0 + (kc << 2);
        cp16(As + off, Ag + gofs);
        cp16(Bs + off, Wg + gofs);
    }
}

template<int EPI>
__device__ __forceinline__ void gemm6_body(
    const float* __restrict__ A, const float* __restrict__ W,
    const float* __restrict__ R, float* __restrict__ C,
    int N, int K)
{
    extern __shared__ __align__(16) float sm6[];

    int t = threadIdx.x;
    int warp = t >> 5, lane = t & 31;
    int wm = warp & 1, wn = warp >> 1;        // 2 x 4 warps, warp tile 64x32
    int g = lane >> 2, q = lane & 3;

    const float* Ag = A + (size_t)(blockIdx.y * 128) * K;
    const float* Wg = W + (size_t)(blockIdx.x * 128) * K;

    float acc[4][4][4];
    #pragma unroll
    for (int i = 0; i < 4; i++)
        #pragma unroll
        for (int j = 0; j < 4; j++)
            #pragma unroll
            for (int c = 0; c < 4; c++) acc[i][j][c] = 0.0f;

    int nk = K >> 5;

    // prologue: chunks 0,1
    g6_fill(Ag, Wg, K, 0,  sm6,              sm6 + 4096,              t); cp_commit();
    g6_fill(Ag, Wg, K, 32, sm6 + STG_FLOATS, sm6 + STG_FLOATS + 4096, t); cp_commit();

    for (int c = 0; c < nk; c++) {
        __syncthreads();                       // all warps done with chunk c-1 (stage (c+2)%3)
        if (c + 2 < nk) {
            int fb = (c + 2) % 3;
            g6_fill(Ag, Wg, K, (c + 2) << 5, sm6 + fb*STG_FLOATS, sm6 + fb*STG_FLOATS + 4096, t);
        }
        cp_commit();
        cp_wait<2>();                          // chunk c's group complete
        __syncthreads();                       // visible to all warps

        const float* As = sm6 + (c % 3) * STG_FLOATS;
        const float* Bs = As + 4096;

        #pragma unroll
        for (int ks = 0; ks < 4; ks++) {
            const float* Ab = As + ks * 1024;
            const float* Bb = Bs + ks * 1024;
            uint32_t af[4][4], bf[4][2];
            #pragma unroll
            for (int mt = 0; mt < 4; mt++) {
                int m = wm*64 + mt*16 + g;
                af[mt][0] = __float_as_uint(Ab[m*4 + q]);
                af[mt][1] = __float_as_uint(Ab[(m+8)*4 + q]);
                af[mt][2] = __float_as_uint(Ab[512 + m*4 + q]);
                af[mt][3] = __float_as_uint(Ab[512 + (m+8)*4 + q]);
            }
            #pragma unroll
            for (int nt = 0; nt < 4; nt++) {
                int n = wn*32 + nt*8 + g;
                bf[nt][0] = __float_as_uint(Bb[n*4 + q]);
                bf[nt][1] = __float_as_uint(Bb[512 + n*4 + q]);
            }
            #pragma unroll
            for (int mt = 0; mt < 4; mt++)
                #pragma unroll
                for (int nt = 0; nt < 4; nt++)
                    mma_tf32(acc[mt][nt][0], acc[mt][nt][1], acc[mt][nt][2], acc[mt][nt][3],
                             af[mt][0], af[mt][1], af[mt][2], af[mt][3],
                             bf[nt][0], bf[nt][1]);
        }
    }

    // epilogue
    int browb = blockIdx.y * 128 + wm * 64;
    int bcolb = blockIdx.x * 128 + wn * 32;
    #pragma unroll
    for (int mt = 0; mt < 4; mt++) {
        #pragma unroll
        for (int nt = 0; nt < 4; nt++) {
            int r0 = browb + mt*16 + g;
            int c0 = bcolb + nt*8 + 2*q;
            #pragma unroll
            for (int half = 0; half < 2; half++) {
                int r = r0 + half*8;
                float vx = acc[mt][nt][half*2 + 0];
                float vy = acc[mt][nt][half*2 + 1];
                size_t base = (size_t)r * N + c0;
                if (EPI == EPI_RND) {
                    vx = rtf(vx); vy = rtf(vy);
                } else if (EPI == EPI_GELU) {
                    vx = rtf(gelu_exact(vx)); vy = rtf(gelu_exact(vy));
                } else {
                    float2 rr = *(const float2*)(R + base);
                    vx += rr.x; vy += rr.y;
                }
                float2 o; o.x = vx; o.y = vy;
                *(float2*)(C + base) = o;
            }
        }
    }
}

template<int EPI>
__global__ __launch_bounds__(256, 2) void gemm6(
    const float* __restrict__ A, const float* __restrict__ W,
    const float* __restrict__ R, float* __restrict__ C,
    int N, int K)
{
    gemm6_body<EPI>(A, W, R, C, N, K);
}

__global__ __launch_bounds__(256, 2) void gemm6_qkv(
    const float* __restrict__ A,
    const float* __restrict__ W0, const float* __restrict__ W1, const float* __restrict__ W2,
    float* __restrict__ C0, float* __restrict__ C1, float* __restrict__ C2)
{
    const float* W = (blockIdx.z == 0) ? W0 : (blockIdx.z == 1) ? W1 : W2;
    float* C = (blockIdx.z == 0) ? C0 : (blockIdx.z == 1) ? C1 : C2;
    gemm6_body<EPI_RND>(A, W, nullptr, C, DMODEL, DMODEL);
}

// ---------------- TF32 mma.sync flash attention, causal ----------------
// Q/K/V tf32-pre-rounded by QKV epilogue; output O rounded.
#define ASD 68

__global__ __launch_bounds__(128) void attn_tc(
    const float* __restrict__ Q, const float* __restrict__ K,
    const float* __restrict__ V, float* __restrict__ O)
{
    extern __shared__ __align__(16) float sm[];
    float* Qs = sm;                 // [64][68]
    float* Ks = sm + 64*ASD;        // [2][64][68]
    float* Vs = sm + 3*64*ASD;      // [2][64][68]
    float* Ps = sm + 5*64*ASD;      // [64][68]

    int qt = blockIdx.x, h = blockIdx.y, b = blockIdx.z;
    int t = threadIdx.x;
    int warp = t >> 5, lane = t & 31;
    int g = lane >> 2, q = lane & 3;

    const float* Qb = Q + ((size_t)b*SEQ + (size_t)qt*64) * DMODEL + h*HD;
    const float* Kb = K + (size_t)b*SEQ*DMODEL + h*HD;
    const float* Vb = V + (size_t)b*SEQ*DMODEL + h*HD;

    // Q tile: scale by 1/8 (exponent-only; Q already tf32)
    for (int i = t; i < 64*16; i += 128) {
        int r = i >> 4, c = (i & 15) * 4;
        float4 v = *(const float4*)(Qb + (size_t)r * DMODEL + c);
        v.x *= 0.125f; v.y *= 0.125f; v.z *= 0.125f; v.w *= 0.125f;
        *(float4*)(Qs + r*ASD + c) = v;
    }

    {
        for (int i = t; i < 64*16; i += 128) {
            int r = i >> 4, c = (i & 15) * 4;
            cp16(&Ks[r*ASD + c], Kb + (size_t)r * DMODEL + c);
            cp16(&Vs[r*ASD + c], Vb + (size_t)r * DMODEL + c);
        }
        cp_commit();
    }

    float acc[8][4];
    #pragma unroll
    for (int nt = 0; nt < 8; nt++)
        #pragma unroll
        for (int c = 0; c < 4; c++) acc[nt][c] = 0.0f;
    float m0 = -1e30f, m1 = -1e30f, l0 = 0.0f, l1 = 0.0f;

    int r0 = 16*warp + g;
    int r1 = r0 + 8;

    for (int kt = 0; kt <= qt; kt++) {
        int buf = kt & 1;
        if (kt < qt) {
            int nbuf = (kt + 1) & 1;
            const float* Kt = Kb + (size_t)(kt+1) * 64 * DMODEL;
            const float* Vt = Vb + (size_t)(kt+1) * 64 * DMODEL;
            float* Kd = Ks + nbuf*64*ASD;
            float* Vd = Vs + nbuf*64*ASD;
            for (int i = t; i < 64*16; i += 128) {
                int r = i >> 4, c = (i & 15) * 4;
                cp16(&Kd[r*ASD + c], Kt + (size_t)r * DMODEL + c);
                cp16(&Vd[r*ASD + c], Vt + (size_t)r * DMODEL + c);
            }
            cp_commit();
            cp_wait<1>();
        } else {
            cp_wait<0>();
        }
        __syncthreads();

        const float* Kbuf = Ks + buf*64*ASD;
        const float* Vbuf = Vs + buf*64*ASD;

        float sc[8][4];
        #pragma unroll
        for (int nt = 0; nt < 8; nt++)
            #pragma unroll
            for (int c = 0; c < 4; c++) sc[nt][c] = 0.0f;

        #pragma unroll
        for (int c8 = 0; c8 < 8; c8++) {
            int kb = c8 * 8;
            uint32_t a0 = __float_as_uint(Qs[(size_t)r0*ASD + kb + q]);
            uint32_t a1 = __float_as_uint(Qs[(size_t)r1*ASD + kb + q]);
            uint32_t a2 = __float_as_uint(Qs[(size_t)r0*ASD + kb + q + 4]);
            uint32_t a3 = __float_as_uint(Qs[(size_t)r1*ASD + kb + q + 4]);
            #pragma unroll
            for (int nt = 0; nt < 8; nt++) {
                uint32_t b0 = __float_as_uint(Kbuf[(size_t)(8*nt+g)*ASD + kb + q]);
                uint32_t b1 = __float_as_uint(Kbuf[(size_t)(8*nt+g)*ASD + kb + q + 4]);
                mma_tf32(sc[nt][0], sc[nt][1], sc[nt][2], sc[nt][3],
                         a0, a1, a2, a3, b0, b1);
            }
        }

        if (kt == qt) {
            #pragma unroll
            for (int nt = 0; nt < 8; nt++) {
                int col0 = 8*nt + 2*q;
                if (col0     > r0) sc[nt][0] = -1e30f;
                if (col0 + 1 > r0) sc[nt][1] = -1e30f;
                if (col0     > r1) sc[nt][2] = -1e30f;
                if (col0 + 1 > r1) sc[nt][3] = -1e30f;
            }
        }

        float tm0 = -1e30f, tm1 = -1e30f;
        #pragma unroll
        for (int nt = 0; nt < 8; nt++) {
            tm0 = fmaxf(tm0, fmaxf(sc[nt][0], sc[nt][1]));
            tm1 = fmaxf(tm1, fmaxf(sc[nt][2], sc[nt][3]));
        }
        tm0 = fmaxf(tm0, __shfl_xor_sync(0xffffffffu, tm0, 1));
        tm0 = fmaxf(tm0, __shfl_xor_sync(0xffffffffu, tm0, 2));
        tm1 = fmaxf(tm1, __shfl_xor_sync(0xffffffffu, tm1, 1));
        tm1 = fmaxf(tm1, __shfl_xor_sync(0xffffffffu, tm1, 2));

        float m0n = fmaxf(m0, tm0);
        float m1n = fmaxf(m1, tm1);
        float corr0 = __expf(m0 - m0n);
        float corr1 = __expf(m1 - m1n);

        float sum0 = 0.0f, sum1 = 0.0f;
        #pragma unroll
        for (int nt = 0; nt < 8; nt++) {
            float p0 = __expf(sc[nt][0] - m0n);
            float p1 = __expf(sc[nt][1] - m0n);
            float p2 = __expf(sc[nt][2] - m1n);
            float p3 = __expf(sc[nt][3] - m1n);
            sum0 += p0 + p1;
            sum1 += p2 + p3;
            float2 w0; w0.x = rtf(p0); w0.y = rtf(p1);
            float2 w1; w1.x = rtf(p2); w1.y = rtf(p3);
            *(float2*)&Ps[(size_t)r0*ASD + 8*nt + 2*q] = w0;
            *(float2*)&Ps[(size_t)r1*ASD + 8*nt + 2*q] = w1;
        }
        sum0 += __shfl_xor_sync(0xffffffffu, sum0, 1);
        sum0 += __shfl_xor_sync(0xffffffffu, sum0, 2);
        sum1 += __shfl_xor_sync(0xffffffffu, sum1, 1);
        sum1 += __shfl_xor_sync(0xffffffffu, sum1, 2);

        l0 = l0 * corr0 + sum0;
        l1 = l1 * corr1 + sum1;
        m0 = m0n; m1 = m1n;
        #pragma unroll
        for (int nt = 0; nt < 8; nt++) {
            acc[nt][0] *= corr0; acc[nt][1] *= corr0;
            acc[nt][2] *= corr1; acc[nt][3] *= corr1;
        }
        __syncwarp();

        #pragma unroll
        for (int c8 = 0; c8 < 8; c8++) {
            int kb = c8 * 8;
            uint32_t a0 = __float_as_uint(Ps[(size_t)r0*ASD + kb + q]);
            uint32_t a1 = __float_as_uint(Ps[(size_t)r1*ASD + kb + q]);
            uint32_t a2 = __float_as_uint(Ps[(size_t)r0*ASD + kb + q + 4]);
            uint32_t a3 = __float_as_uint(Ps[(size_t)r1*ASD + kb + q + 4]);
            #pragma unroll
            for (int nt = 0; nt < 8; nt++) {
                uint32_t b0 = __float_as_uint(Vbuf[(size_t)(kb+q)*ASD + 8*nt + g]);
                uint32_t b1 = __float_as_uint(Vbuf[(size_t)(kb+q+4)*ASD + 8*nt + g]);
                mma_tf32(acc[nt][0], acc[nt][1], acc[nt][2], acc[nt][3],
                         a0, a1, a2, a3, b0, b1);
            }
        }
        __syncthreads();
    }

    float inv0 = 1.0f / l0;
    float inv1 = 1.0f / l1;
    float* Ob = O + ((size_t)b*SEQ + (size_t)qt*64) * DMODEL + h*HD;
    #pragma unroll
    for (int nt = 0; nt < 8; nt++) {
        int col = 8*nt + 2*q;
        float2 o0; o0.x = rtf(acc[nt][0]*inv0); o0.y = rtf(acc[nt][1]*inv0);
        float2 o1; o1.x = rtf(acc[nt][2]*inv1); o1.y = rtf(acc[nt][3]*inv1);
        *(float2*)(Ob + (size_t)r0 * DMODEL + col) = o0;
        *(float2*)(Ob + (size_t)r1 * DMODEL + col) = o1;
    }
}

// ---------------- launch ----------------
extern "C" void kernel_launch(void* const* d_in, const int* in_sizes, int n_in,
                              void* d_out, int out_size)
{
    const float* x    = (const float*)d_in[0];
    const float* Wq   = (const float*)d_in[1];
    const float* Wk   = (const float*)d_in[2];
    const float* Wv   = (const float*)d_in[3];
    const float* Wo   = (const float*)d_in[4];
    const float* Wup  = (const float*)d_in[5];
    const float* Wdn  = (const float*)d_in[6];
    const float* ln1m = (const float*)d_in[7];
    const float* ln1s = (const float*)d_in[8];
    const float* ln2m = (const float*)d_in[9];
    const float* ln2s = (const float*)d_in[10];
    float* out = (float*)d_out;

    float *b0, *b1, *b2, *b3, *b4, *bm;
    float *wq, *wk, *wv, *wo, *wup, *wdn;
    cudaGetSymbolAddress((void**)&b0, g_buf0);
    cudaGetSymbolAddress((void**)&b1, g_buf1);
    cudaGetSymbolAddress((void**)&b2, g_buf2);
    cudaGetSymbolAddress((void**)&b3, g_buf3);
    cudaGetSymbolAddress((void**)&b4, g_buf4);
    cudaGetSymbolAddress((void**)&bm, g_mid);
    cudaGetSymbolAddress((void**)&wq, g_wq);
    cudaGetSymbolAddress((void**)&wk, g_wk);
    cudaGetSymbolAddress((void**)&wv, g_wv);
    cudaGetSymbolAddress((void**)&wo, g_wo);
    cudaGetSymbolAddress((void**)&wup, g_wup);
    cudaGetSymbolAddress((void**)&wdn, g_wdn);

    cudaFuncSetAttribute(gemm6<EPI_RND>,  cudaFuncAttributeMaxDynamicSharedMemorySize, G6_SMEM);
    cudaFuncSetAttribute(gemm6<EPI_GELU>, cudaFuncAttributeMaxDynamicSharedMemorySize, G6_SMEM);
    cudaFuncSetAttribute(gemm6<EPI_ADD>,  cudaFuncAttributeMaxDynamicSharedMemorySize, G6_SMEM);
    cudaFuncSetAttribute(gemm6_qkv,       cudaFuncAttributeMaxDynamicSharedMemorySize, G6_SMEM);

    const int attn_smem = 6 * 64 * ASD * (int)sizeof(float);     // 104448 B
    cudaFuncSetAttribute(attn_tc, cudaFuncAttributeMaxDynamicSharedMemorySize, attn_smem);

    const int NP = DMODEL*DMODEL/4/256;
    const int NB = DFF*DMODEL/4/256;

    // round weights to tf32
    round_kernel<<<NP, 256>>>(Wq, wq, DMODEL*DMODEL/4);
    round_kernel<<<NP, 256>>>(Wk, wk, DMODEL*DMODEL/4);
    round_kernel<<<NP, 256>>>(Wv, wv, DMODEL*DMODEL/4);
    round_kernel<<<NP, 256>>>(Wo, wo, DMODEL*DMODEL/4);
    round_kernel<<<NB, 256>>>(Wup, wup, DFF*DMODEL/4);
    round_kernel<<<NB, 256>>>(Wdn, wdn, DMODEL*DFF/4);

    dim3 gproj(DMODEL/128, MROWS/128);      // (8, 32)
    dim3 gqkv (DMODEL/128, MROWS/128, 3);
    dim3 gup  (DFF/128,    MROWS/128);      // (32, 32)

    // LN1 (tf32-rounded out)
    ln_kernel<<<MROWS, 256>>>(x, ln1m, ln1s, b0);
    // fused QKV (rounded out)
    gemm6_qkv<<<gqkv, 256, G6_SMEM>>>(b0, wq, wk, wv, b1, b2, b3);
    // flash attention (rounded out, overwrites b0)
    attn_tc<<<dim3(SEQ/64, NH, BDIM), 128, attn_smem>>>(b1, b2, b3, b0);
    // out proj + residual -> y1
    gemm6<EPI_ADD><<<gproj, 256, G6_SMEM>>>(b0, wo, x, b4, DMODEL, DMODEL);
    // LN2 (rounded out)
    ln_kernel<<<MROWS, 256>>>(b4, ln2m, ln2s, b1);
    // MLP up + GELU (rounded out)
    gemm6<EPI_GELU><<<gup, 256, G6_SMEM>>>(b1, wup, nullptr, bm, DFF, DMODEL);
    // MLP down + residual -> out
    gemm6<EPI_ADD><<<gproj, 256, G6_SMEM>>>(bm, wdn, b4, out, DMODEL, DFF);
}

// round 9
// speedup vs baseline: 2.4001x; 2.4001x over previous
#include <cuda_runtime.h>
#include <cuda_fp16.h>
#include <math.h>
#include <stdint.h>

#define BDIM 2
#define SEQ  2048
#define DMODEL 1024
#define NH   16
#define HD   64
#define MROWS (BDIM*SEQ)     // 4096
#define DFF  4096
#define LN_EPS 1e-9f

// ---------------- scratch ----------------
__device__ float g_buf1[(size_t)MROWS*DMODEL];   // Q (fp32, tf32-rounded)
__device__ float g_buf2[(size_t)MROWS*DMODEL];   // K
__device__ float g_buf3[(size_t)MROWS*DMODEL];   // V
__device__ float g_buf4[(size_t)MROWS*DMODEL];   // y1 = x + attn
__device__ __half g_hln1[(size_t)MROWS*DMODEL];  // ln1 out (half)
__device__ __half g_hO  [(size_t)MROWS*DMODEL];  // attention O (half)
__device__ __half g_hln2[(size_t)MROWS*DMODEL];  // ln2 out (half)
__device__ __half g_hmid[(size_t)MROWS*DFF];     // MLP mid (half)
// half weights
__device__ __half g_hwq[(size_t)DMODEL*DMODEL];
__device__ __half g_hwk[(size_t)DMODEL*DMODEL];
__device__ __half g_hwv[(size_t)DMODEL*DMODEL];
__device__ __half g_hwo[(size_t)DMODEL*DMODEL];
__device__ __half g_hwup[(size_t)DFF*DMODEL];
__device__ __half g_hwdn[(size_t)DMODEL*DFF];

// ---------------- helpers ----------------
__device__ __forceinline__ uint32_t f2tf32(float x) {
    uint32_t u; asm("cvt.rna.tf32.f32 %0, %1;" : "=r"(u) : "f"(x));
    return u;
}
__device__ __forceinline__ float rtf(float x) { return __uint_as_float(f2tf32(x)); }

__device__ __forceinline__ void cp16(void* s, const void* g) {
    uint32_t sa = (uint32_t)__cvta_generic_to_shared(s);
    asm volatile("cp.async.cg.shared.global [%0], [%1], 16;" :: "r"(sa), "l"(g));
}
__device__ __forceinline__ void cp_commit() {
    asm volatile("cp.async.commit_group;");
}
template<int NGRP> __device__ __forceinline__ void cp_wait() {
    asm volatile("cp.async.wait_group %0;" :: "n"(NGRP));
}
__device__ __forceinline__ float gelu_exact(float v) {
    return 0.5f * v * (1.0f + erff(v * 0.7071067811865476f));
}
__device__ __forceinline__ void mma_tf32(
    float& c0, float& c1, float& c2, float& c3,
    uint32_t a0, uint32_t a1, uint32_t a2, uint32_t a3,
    uint32_t b0, uint32_t b1)
{
    asm volatile(
        "mma.sync.aligned.m16n8k8.row.col.f32.tf32.tf32.f32 "
        "{%0,%1,%2,%3}, {%4,%5,%6,%7}, {%8,%9}, {%0,%1,%2,%3};"
        : "+f"(c0), "+f"(c1), "+f"(c2), "+f"(c3)
        : "r"(a0), "r"(a1), "r"(a2), "r"(a3), "r"(b0), "r"(b1));
}
__device__ __forceinline__ void mma_f16(
    float& c0, float& c1, float& c2, float& c3,
    uint32_t a0, uint32_t a1, uint32_t a2, uint32_t a3,
    uint32_t b0, uint32_t b1)
{
    asm volatile(
        "mma.sync.aligned.m16n8k16.row.col.f32.f16.f16.f32 "
        "{%0,%1,%2,%3}, {%4,%5,%6,%7}, {%8,%9}, {%0,%1,%2,%3};"
        : "+f"(c0), "+f"(c1), "+f"(c2), "+f"(c3)
        : "r"(a0), "r"(a1), "r"(a2), "r"(a3), "r"(b0), "r"(b1));
}

// ---------------- weight conversion fp32 -> fp16 ----------------
__global__ __launch_bounds__(256) void convh_kernel(const float* __restrict__ in,
                                                    __half* __restrict__ out, int n4) {
    int i = blockIdx.x * blockDim.x + threadIdx.x;
    if (i < n4) {
        float4 v = ((const float4*)in)[i];
        __half2* o = (__half2*)out + 2*(size_t)i;
        o[0] = __floats2half2_rn(v.x, v.y);
        o[1] = __floats2half2_rn(v.z, v.w);
    }
}

// ---------------- LayerNorm (ddof=1), output fp16 ----------------
__global__ __launch_bounds__(256) void ln_h_kernel(
    const float* __restrict__ x, const float* __restrict__ mean_scale,
    const float* __restrict__ std_scale, __half* __restrict__ out)
{
    int row = blockIdx.x;
    int t = threadIdx.x;
    const float4* xr = (const float4*)(x + (size_t)row*DMODEL);
    float4 v = xr[t];

    __shared__ float red[8];
    float s = v.x + v.y + v.z + v.w;
    #pragma unroll
    for (int m = 16; m > 0; m >>= 1) s += __shfl_xor_sync(0xffffffffu, s, m);
    if ((t & 31) == 0) red[t >> 5] = s;
    __syncthreads();
    if (t < 8) {
        float r = red[t];
        #pragma unroll
        for (int m = 4; m > 0; m >>= 1) r += __shfl_xor_sync(0xffu, r, m);
        if (t == 0) red[0] = r;
    }
    __syncthreads();
    float mean = red[0] * (1.0f / DMODEL);
    float dx = v.x - mean, dy = v.y - mean, dz = v.z - mean, dw = v.w - mean;
    float q = dx*dx + dy*dy + dz*dz + dw*dw;
    __syncthreads();
    #pragma unroll
    for (int m = 16; m > 0; m >>= 1) q += __shfl_xor_sync(0xffffffffu, q, m);
    if ((t & 31) == 0) red[t >> 5] = q;
    __syncthreads();
    if (t < 8) {
        float r = red[t];
        #pragma unroll
        for (int m = 4; m > 0; m >>= 1) r += __shfl_xor_sync(0xffu, r, m);
        if (t == 0) red[0] = r;
    }
    __syncthreads();
    float var = red[0] * (1.0f / (DMODEL - 1));
    float rstd = rsqrtf(var + LN_EPS);

    float4 msv = ((const float4*)mean_scale)[t];
    float4 ssv = ((const float4*)std_scale)[t];
    __half2* o = (__half2*)(out + (size_t)row*DMODEL) + 2*t;
    o[0] = __floats2half2_rn(dx * rstd * ssv.x + msv.x, dy * rstd * ssv.y + msv.y);
    o[1] = __floats2half2_rn(dz * rstd * ssv.z + msv.z, dw * rstd * ssv.w + msv.w);
}

// ---------------- FP16 mma.sync GEMM (round-4 proven layout) ----------------
// C[m,n] = sum_k A[m,k]*W[n,k] (+epi). A,W fp16. Tile 128x128, K-chunk 64 halves.
// smem: float-slot array, row stride 36 floats (=72 halves, 144B):
//  conflict-free on both cp.async stores and fragment LDS (bank = 4m+q perm).
#define EPI_RND  0   // write rtf(fp32) to Cf (attention tf32 inputs)
#define EPI_GELU 1   // write gelu as half to Ch
#define EPI_ADD  2   // write fp32 + R to Cf

#define TSTR 36
#define TILE_FLOATS (128*TSTR)   // 4608 float slots per (matrix, stage)
#define GH_SMEM (4 * TILE_FLOATS * 4)   // 73728 B

__device__ __forceinline__ void fill_h(
    const __half* __restrict__ Ag, const __half* __restrict__ Wg, int K, int k0,
    float* __restrict__ As, float* __restrict__ Bs, int t)
{
    #pragma unroll
    for (int i = 0; i < 4; i++) {
        int lin = t + i * 256;
        int row = lin >> 3, u = lin & 7;          // u: 16B chunk within 128B row
        cp16(As + row*TSTR + u*4, Ag + (size_t)row * K + k0 + u*8);
        cp16(Bs + row*TSTR + u*4, Wg + (size_t)row * K + k0 + u*8);
    }
}

template<int EPI>
__device__ __forceinline__ void gemmh_body(
    const __half* __restrict__ A, const __half* __restrict__ W,
    const float* __restrict__ R, float* __restrict__ Cf, __half* __restrict__ Ch,
    int N, int K)
{
    extern __shared__ __align__(16) float smem[];
    float* As = smem;                    // [2][128][36] float slots (half2)
    float* Bs = smem + 2*TILE_FLOATS;

    int t = threadIdx.x;
    int warp = t >> 5, lane = t & 31;
    int wm = warp & 1, wn = warp >> 1;   // 2 x 4 warps, warp tile 64x32
    int g = lane >> 2, q = lane & 3;

    const __half* Ag = A + (size_t)(blockIdx.y * 128) * K;
    const __half* Wg = W + (size_t)(blockIdx.x * 128) * K;

    float acc[4][4][4];
    #pragma unroll
    for (int i = 0; i < 4; i++)
        #pragma unroll
        for (int j = 0; j < 4; j++)
            #pragma unroll
            for (int c = 0; c < 4; c++) acc[i][j][c] = 0.0f;

    int nk = K >> 6;   // 64-half chunks

    fill_h(Ag, Wg, K, 0, As, Bs, t);
    cp_commit();

    for (int kt = 0; kt < nk; kt++) {
        int buf = kt & 1;
        if (kt + 1 < nk) {
            int nbuf = (kt + 1) & 1;
            fill_h(Ag, Wg, K, (kt + 1) << 6,
                   As + nbuf*TILE_FLOATS, Bs + nbuf*TILE_FLOATS, t);
            cp_commit();
            cp_wait<1>();
        } else {
            cp_wait<0>();
        }
        __syncthreads();

        const float* Abs = As + buf * TILE_FLOATS;
        const float* Bbs = Bs + buf * TILE_FLOATS;
        #pragma unroll
        for (int ks = 0; ks < 4; ks++) {       // 16 halves (8 float slots) per step
            int kb = ks * 8;
            uint32_t af[4][4], bf[4][2];
            #pragma unroll
            for (int mt = 0; mt < 4; mt++) {
                int m = wm*64 + mt*16 + g;
                af[mt][0] = __float_as_uint(Abs[m*TSTR + kb + q]);
                af[mt][1] = __float_as_uint(Abs[(m+8)*TSTR + kb + q]);
                af[mt][2] = __float_as_uint(Abs[m*TSTR + kb + q + 4]);
                af[mt][3] = __float_as_uint(Abs[(m+8)*TSTR + kb + q + 4]);
            }
            #pragma unroll
            for (int nt = 0; nt < 4; nt++) {
                int n = wn*32 + nt*8 + g;
                bf[nt][0] = __float_as_uint(Bbs[n*TSTR + kb + q]);
                bf[nt][1] = __float_as_uint(Bbs[n*TSTR + kb + q + 4]);
            }
            #pragma unroll
            for (int mt = 0; mt < 4; mt++)
                #pragma unroll
                for (int nt = 0; nt < 4; nt++)
                    mma_f16(acc[mt][nt][0], acc[mt][nt][1], acc[mt][nt][2], acc[mt][nt][3],
                            af[mt][0], af[mt][1], af[mt][2], af[mt][3],
                            bf[nt][0], bf[nt][1]);
        }
        __syncthreads();
    }

    int browb = blockIdx.y * 128 + wm * 64;
    int bcolb = blockIdx.x * 128 + wn * 32;
    #pragma unroll
    for (int mt = 0; mt < 4; mt++) {
        #pragma unroll
        for (int nt = 0; nt < 4; nt++) {
            int r0 = browb + mt*16 + g;
            int c0 = bcolb + nt*8 + 2*q;
            #pragma unroll
            for (int half = 0; half < 2; half++) {
                int r = r0 + half*8;
                float vx = acc[mt][nt][half*2 + 0];
                float vy = acc[mt][nt][half*2 + 1];
                size_t base = (size_t)r * N + c0;
                if (EPI == EPI_RND) {
                    float2 o; o.x = rtf(vx); o.y = rtf(vy);
                    *(float2*)(Cf + base) = o;
                } else if (EPI == EPI_GELU) {
                    *(__half2*)(Ch + base) =
                        __floats2half2_rn(gelu_exact(vx), gelu_exact(vy));
                } else {
                    float2 rr = *(const float2*)(R + base);
                    float2 o; o.x = vx + rr.x; o.y = vy + rr.y;
                    *(float2*)(Cf + base) = o;
                }
            }
        }
    }
}

template<int EPI>
__global__ __launch_bounds__(256, 2) void gemmh(
    const __half* __restrict__ A, const __half* __restrict__ W,
    const float* __restrict__ R, float* __restrict__ Cf, __half* __restrict__ Ch,
    int N, int K)
{
    gemmh_body<EPI>(A, W, R, Cf, Ch, N, K);
}

__global__ __launch_bounds__(256, 2) void gemmh_qkv(
    const __half* __restrict__ A,
    const __half* __restrict__ W0, const __half* __restrict__ W1, const __half* __restrict__ W2,
    float* __restrict__ C0, float* __restrict__ C1, float* __restrict__ C2)
{
    const __half* W = (blockIdx.z == 0) ? W0 : (blockIdx.z == 1) ? W1 : W2;
    float* C = (blockIdx.z == 0) ? C0 : (blockIdx.z == 1) ? C1 : C2;
    gemmh_body<EPI_RND>(A, W, nullptr, C, nullptr, DMODEL, DMODEL);
}

// ---------------- TF32 mma.sync flash attention, causal (round-4 proven) ----------------
// Q/K/V fp32 tf32-pre-rounded; output O written as fp16.
#define ASD 68

__global__ __launch_bounds__(128) void attn_tc(
    const float* __restrict__ Q, const float* __restrict__ K,
    const float* __restrict__ V, __half* __restrict__ O)
{
    extern __shared__ __align__(16) float sm[];
    float* Qs = sm;                 // [64][68]
    float* Ks = sm + 64*ASD;        // [2][64][68]
    float* Vs = sm + 3*64*ASD;      // [2][64][68]
    float* Ps = sm + 5*64*ASD;      // [64][68]

    int qt = blockIdx.x, h = blockIdx.y, b = blockIdx.z;
    int t = threadIdx.x;
    int warp = t >> 5, lane = t & 31;
    int g = lane >> 2, q = lane & 3;

    const float* Qb = Q + ((size_t)b*SEQ + (size_t)qt*64) * DMODEL + h*HD;
    const float* Kb = K + (size_t)b*SEQ*DMODEL + h*HD;
    const float* Vb = V + (size_t)b*SEQ*DMODEL + h*HD;

    for (int i = t; i < 64*16; i += 128) {
        int r = i >> 4, c = (i & 15) * 4;
        float4 v = *(const float4*)(Qb + (size_t)r * DMODEL + c);
        v.x *= 0.125f; v.y *= 0.125f; v.z *= 0.125f; v.w *= 0.125f;
        *(float4*)(Qs + r*ASD + c) = v;
    }

    {
        for (int i = t; i < 64*16; i += 128) {
            int r = i >> 4, c = (i & 15) * 4;
            cp16(&Ks[r*ASD + c], Kb + (size_t)r * DMODEL + c);
            cp16(&Vs[r*ASD + c], Vb + (size_t)r * DMODEL + c);
        }
        cp_commit();
    }

    float acc[8][4];
    #pragma unroll
    for (int nt = 0; nt < 8; nt++)
        #pragma unroll
        for (int c = 0; c < 4; c++) acc[nt][c] = 0.0f;
    float m0 = -1e30f, m1 = -1e30f, l0 = 0.0f, l1 = 0.0f;

    int r0 = 16*warp + g;
    int r1 = r0 + 8;

    for (int kt = 0; kt <= qt; kt++) {
        int buf = kt & 1;
        if (kt < qt) {
            int nbuf = (kt + 1) & 1;
            const float* Kt = Kb + (size_t)(kt+1) * 64 * DMODEL;
            const float* Vt = Vb + (size_t)(kt+1) * 64 * DMODEL;
            float* Kd = Ks + nbuf*64*ASD;
            float* Vd = Vs + nbuf*64*ASD;
            for (int i = t; i < 64*16; i += 128) {
                int r = i >> 4, c = (i & 15) * 4;
                cp16(&Kd[r*ASD + c], Kt + (size_t)r * DMODEL + c);
                cp16(&Vd[r*ASD + c], Vt + (size_t)r * DMODEL + c);
            }
            cp_commit();
            cp_wait<1>();
        } else {
            cp_wait<0>();
        }
        __syncthreads();

        const float* Kbuf = Ks + buf*64*ASD;
        const float* Vbuf = Vs + buf*64*ASD;

        float sc[8][4];
        #pragma unroll
        for (int nt = 0; nt < 8; nt++)
            #pragma unroll
            for (int c = 0; c < 4; c++) sc[nt][c] = 0.0f;

        #pragma unroll
        for (int c8 = 0; c8 < 8; c8++) {
            int kb = c8 * 8;
            uint32_t a0 = __float_as_uint(Qs[(size_t)r0*ASD + kb + q]);
            uint32_t a1 = __float_as_uint(Qs[(size_t)r1*ASD + kb + q]);
            uint32_t a2 = __float_as_uint(Qs[(size_t)r0*ASD + kb + q + 4]);
            uint32_t a3 = __float_as_uint(Qs[(size_t)r1*ASD + kb + q + 4]);
            #pragma unroll
            for (int nt = 0; nt < 8; nt++) {
                uint32_t b0 = __float_as_uint(Kbuf[(size_t)(8*nt+g)*ASD + kb + q]);
                uint32_t b1 = __float_as_uint(Kbuf[(size_t)(8*nt+g)*ASD + kb + q + 4]);
                mma_tf32(sc[nt][0], sc[nt][1], sc[nt][2], sc[nt][3],
                         a0, a1, a2, a3, b0, b1);
            }
        }

        if (kt == qt) {
            #pragma unroll
            for (int nt = 0; nt < 8; nt++) {
                int col0 = 8*nt + 2*q;
                if (col0     > r0) sc[nt][0] = -1e30f;
                if (col0 + 1 > r0) sc[nt][1] = -1e30f;
                if (col0     > r1) sc[nt][2] = -1e30f;
                if (col0 + 1 > r1) sc[nt][3] = -1e30f;
            }
        }

        float tm0 = -1e30f, tm1 = -1e30f;
        #pragma unroll
        for (int nt = 0; nt < 8; nt++) {
            tm0 = fmaxf(tm0, fmaxf(sc[nt][0], sc[nt][1]));
            tm1 = fmaxf(tm1, fmaxf(sc[nt][2], sc[nt][3]));
        }
        tm0 = fmaxf(tm0, __shfl_xor_sync(0xffffffffu, tm0, 1));
        tm0 = fmaxf(tm0, __shfl_xor_sync(0xffffffffu, tm0, 2));
        tm1 = fmaxf(tm1, __shfl_xor_sync(0xffffffffu, tm1, 1));
        tm1 = fmaxf(tm1, __shfl_xor_sync(0xffffffffu, tm1, 2));

        float m0n = fmaxf(m0, tm0);
        float m1n = fmaxf(m1, tm1);
        float corr0 = __expf(m0 - m0n);
        float corr1 = __expf(m1 - m1n);

        float sum0 = 0.0f, sum1 = 0.0f;
        #pragma unroll
        for (int nt = 0; nt < 8; nt++) {
            float p0 = __expf(sc[nt][0] - m0n);
            float p1 = __expf(sc[nt][1] - m0n);
            float p2 = __expf(sc[nt][2] - m1n);
            float p3 = __expf(sc[nt][3] - m1n);
            sum0 += p0 + p1;
            sum1 += p2 + p3;
            float2 w0; w0.x = rtf(p0); w0.y = rtf(p1);
            float2 w1; w1.x = rtf(p2); w1.y = rtf(p3);
            *(float2*)&Ps[(size_t)r0*ASD + 8*nt + 2*q] = w0;
            *(float2*)&Ps[(size_t)r1*ASD + 8*nt + 2*q] = w1;
        }
        sum0 += __shfl_xor_sync(0xffffffffu, sum0, 1);
        sum0 += __shfl_xor_sync(0xffffffffu, sum0, 2);
        sum1 += __shfl_xor_sync(0xffffffffu, sum1, 1);
        sum1 += __shfl_xor_sync(0xffffffffu, sum1, 2);

        l0 = l0 * corr0 + sum0;
        l1 = l1 * corr1 + sum1;
        m0 = m0n; m1 = m1n;
        #pragma unroll
        for (int nt = 0; nt < 8; nt++) {
            acc[nt][0] *= corr0; acc[nt][1] *= corr0;
            acc[nt][2] *= corr1; acc[nt][3] *= corr1;
        }
        __syncwarp();

        #pragma unroll
        for (int c8 = 0; c8 < 8; c8++) {
            int kb = c8 * 8;
            uint32_t a0 = __float_as_uint(Ps[(size_t)r0*ASD + kb + q]);
            uint32_t a1 = __float_as_uint(Ps[(size_t)r1*ASD + kb + q]);
            uint32_t a2 = __float_as_uint(Ps[(size_t)r0*ASD + kb + q + 4]);
            uint32_t a3 = __float_as_uint(Ps[(size_t)r1*ASD + kb + q + 4]);
            #pragma unroll
            for (int nt = 0; nt < 8; nt++) {
                uint32_t b0 = __float_as_uint(Vbuf[(size_t)(kb+q)*ASD + 8*nt + g]);
                uint32_t b1 = __float_as_uint(Vbuf[(size_t)(kb+q+4)*ASD + 8*nt + g]);
                mma_tf32(acc[nt][0], acc[nt][1], acc[nt][2], acc[nt][3],
                         a0, a1, a2, a3, b0, b1);
            }
        }
        __syncthreads();
    }

    float inv0 = 1.0f / l0;
    float inv1 = 1.0f / l1;
    __half* Ob = O + ((size_t)b*SEQ + (size_t)qt*64) * DMODEL + h*HD;
    #pragma unroll
    for (int nt = 0; nt < 8; nt++) {
        int col = 8*nt + 2*q;
        *(__half2*)(Ob + (size_t)r0 * DMODEL + col) =
            __floats2half2_rn(acc[nt][0]*inv0, acc[nt][1]*inv0);
        *(__half2*)(Ob + (size_t)r1 * DMODEL + col) =
            __floats2half2_rn(acc[nt][2]*inv1, acc[nt][3]*inv1);
    }
}

// ---------------- launch ----------------
extern "C" void kernel_launch(void* const* d_in, const int* in_sizes, int n_in,
                              void* d_out, int out_size)
{
    const float* x    = (const float*)d_in[0];
    const float* Wq   = (const float*)d_in[1];
    const float* Wk   = (const float*)d_in[2];
    const float* Wv   = (const float*)d_in[3];
    const float* Wo   = (const float*)d_in[4];
    const float* Wup  = (const float*)d_in[5];
    const float* Wdn  = (const float*)d_in[6];
    const float* ln1m = (const float*)d_in[7];
    const float* ln1s = (const float*)d_in[8];
    const float* ln2m = (const float*)d_in[9];
    const float* ln2s = (const float*)d_in[10];
    float* out = (float*)d_out;

    float *b1, *b2, *b3, *b4;
    __half *hln1, *hO, *hln2, *hmid, *hwq, *hwk, *hwv, *hwo, *hwup, *hwdn;
    cudaGetSymbolAddress((void**)&b1, g_buf1);
    cudaGetSymbolAddress((void**)&b2, g_buf2);
    cudaGetSymbolAddress((void**)&b3, g_buf3);
    cudaGetSymbolAddress((void**)&b4, g_buf4);
    cudaGetSymbolAddress((void**)&hln1, g_hln1);
    cudaGetSymbolAddress((void**)&hO,   g_hO);
    cudaGetSymbolAddress((void**)&hln2, g_hln2);
    cudaGetSymbolAddress((void**)&hmid, g_hmid);
    cudaGetSymbolAddress((void**)&hwq,  g_hwq);
    cudaGetSymbolAddress((void**)&hwk,  g_hwk);
    cudaGetSymbolAddress((void**)&hwv,  g_hwv);
    cudaGetSymbolAddress((void**)&hwo,  g_hwo);
    cudaGetSymbolAddress((void**)&hwup, g_hwup);
    cudaGetSymbolAddress((void**)&hwdn, g_hwdn);

    cudaFuncSetAttribute(gemmh<EPI_RND>,  cudaFuncAttributeMaxDynamicSharedMemorySize, GH_SMEM);
    cudaFuncSetAttribute(gemmh<EPI_GELU>, cudaFuncAttributeMaxDynamicSharedMemorySize, GH_SMEM);
    cudaFuncSetAttribute(gemmh<EPI_ADD>,  cudaFuncAttributeMaxDynamicSharedMemorySize, GH_SMEM);
    cudaFuncSetAttribute(gemmh_qkv,       cudaFuncAttributeMaxDynamicSharedMemorySize, GH_SMEM);

    const int attn_smem = 6 * 64 * ASD * (int)sizeof(float);     // 104448 B
    cudaFuncSetAttribute(attn_tc, cudaFuncAttributeMaxDynamicSharedMemorySize, attn_smem);

    const int NP = DMODEL*DMODEL/4/256;
    const int NB = DFF*DMODEL/4/256;

    // convert weights to fp16
    convh_kernel<<<NP, 256>>>(Wq, hwq, DMODEL*DMODEL/4);
    convh_kernel<<<NP, 256>>>(Wk, hwk, DMODEL*DMODEL/4);
    convh_kernel<<<NP, 256>>>(Wv, hwv, DMODEL*DMODEL/4);
    convh_kernel<<<NP, 256>>>(Wo, hwo, DMODEL*DMODEL/4);
    convh_kernel<<<NB, 256>>>(Wup, hwup, DFF*DMODEL/4);
    convh_kernel<<<NB, 256>>>(Wdn, hwdn, DMODEL*DFF/4);

    dim3 gproj(DMODEL/128, MROWS/128);      // (8, 32)
    dim3 gqkv (DMODEL/128, MROWS/128, 3);
    dim3 gup  (DFF/128,    MROWS/128);      // (32, 32)

    // LN1 -> fp16
    ln_h_kernel<<<MROWS, 256>>>(x, ln1m, ln1s, hln1);
    // fused QKV (fp16 in, tf32-rounded fp32 out)
    gemmh_qkv<<<gqkv, 256, GH_SMEM>>>(hln1, hwq, hwk, hwv, b1, b2, b3);
    // flash attention (tf32), fp16 out
    attn_tc<<<dim3(SEQ/64, NH, BDIM), 128, attn_smem>>>(b1, b2, b3, hO);
    // out proj + residual -> y1 (fp32)
    gemmh<EPI_ADD><<<gproj, 256, GH_SMEM>>>(hO, hwo, x, b4, nullptr, DMODEL, DMODEL);
    // LN2 -> fp16
    ln_h_kernel<<<MROWS, 256>>>(b4, ln2m, ln2s, hln2);
    // MLP up + GELU -> fp16 mid
    gemmh<EPI_GELU><<<gup, 256, GH_SMEM>>>(hln2, hwup, nullptr, nullptr, hmid, DFF, DMODEL);
    // MLP down + residual -> out (fp32)
    gemmh<EPI_ADD><<<gproj, 256, GH_SMEM>>>(hmid, hwdn, b4, out, nullptr, DMODEL, DFF);
}

// round 14
// speedup vs baseline: 3.0004x; 1.2501x over previous
#include <cuda_runtime.h>
#include <cuda_fp16.h>
#include <math.h>
#include <stdint.h>

#define BDIM 2
#define SEQ  2048
#define DMODEL 1024
#define NH   16
#define HD   64
#define MROWS (BDIM*SEQ)     // 4096
#define DFF  4096
#define LN_EPS 1e-9f

// ---------------- scratch ----------------
__device__ float g_buf4[(size_t)MROWS*DMODEL];   // y1 = x + attn (fp32)
__device__ __half g_hln1[(size_t)MROWS*DMODEL];  // ln1 out
__device__ __half g_hq [(size_t)MROWS*DMODEL];   // Q (half, pre-scaled 1/8)
__device__ __half g_hk [(size_t)MROWS*DMODEL];   // K
__device__ __half g_hv [(size_t)MROWS*DMODEL];   // V
__device__ __half g_hO [(size_t)MROWS*DMODEL];   // attention O
__device__ __half g_hln2[(size_t)MROWS*DMODEL];  // ln2 out
__device__ __half g_hmid[(size_t)MROWS*DFF];     // MLP mid
// half weights
__device__ __half g_hwq[(size_t)DMODEL*DMODEL];
__device__ __half g_hwk[(size_t)DMODEL*DMODEL];
__device__ __half g_hwv[(size_t)DMODEL*DMODEL];
__device__ __half g_hwo[(size_t)DMODEL*DMODEL];
__device__ __half g_hwup[(size_t)DFF*DMODEL];
__device__ __half g_hwdn[(size_t)DMODEL*DFF];

// ---------------- helpers ----------------
__device__ __forceinline__ void cp16(void* s, const void* g) {
    uint32_t sa = (uint32_t)__cvta_generic_to_shared(s);
    asm volatile("cp.async.cg.shared.global [%0], [%1], 16;" :: "r"(sa), "l"(g));
}
__device__ __forceinline__ void cp_commit() {
    asm volatile("cp.async.commit_group;");
}
template<int NGRP> __device__ __forceinline__ void cp_wait() {
    asm volatile("cp.async.wait_group %0;" :: "n"(NGRP));
}
__device__ __forceinline__ float gelu_exact(float v) {
    return 0.5f * v * (1.0f + erff(v * 0.7071067811865476f));
}
__device__ __forceinline__ void mma_f16(
    float& c0, float& c1, float& c2, float& c3,
    uint32_t a0, uint32_t a1, uint32_t a2, uint32_t a3,
    uint32_t b0, uint32_t b1)
{
    asm volatile(
        "mma.sync.aligned.m16n8k16.row.col.f32.f16.f16.f32 "
        "{%0,%1,%2,%3}, {%4,%5,%6,%7}, {%8,%9}, {%0,%1,%2,%3};"
        : "+f"(c0), "+f"(c1), "+f"(c2), "+f"(c3)
        : "r"(a0), "r"(a1), "r"(a2), "r"(a3), "r"(b0), "r"(b1));
}

// ---------------- merged weight conversion fp32 -> fp16 ----------------
__global__ __launch_bounds__(256) void convall_kernel(
    const float* __restrict__ q, const float* __restrict__ k,
    const float* __restrict__ v, const float* __restrict__ o,
    const float* __restrict__ up, const float* __restrict__ dn,
    __half* hq, __half* hk, __half* hv, __half* ho,
    __half* hup, __half* hdn)
{
    int bid = blockIdx.x;
    const float* src; __half* dst; int rel;
    if      (bid < 1024) { src = q;  dst = hq;  rel = bid; }
    else if (bid < 2048) { src = k;  dst = hk;  rel = bid - 1024; }
    else if (bid < 3072) { src = v;  dst = hv;  rel = bid - 2048; }
    else if (bid < 4096) { src = o;  dst = ho;  rel = bid - 3072; }
    else if (bid < 8192) { src = up; dst = hup; rel = bid - 4096; }
    else                 { src = dn; dst = hdn; rel = bid - 8192; }
    size_t i = (size_t)rel * 256 + threadIdx.x;
    float4 vv = ((const float4*)src)[i];
    __half2* outp = (__half2*)dst + 2*i;
    outp[0] = __floats2half2_rn(vv.x, vv.y);
    outp[1] = __floats2half2_rn(vv.z, vv.w);
}

// ---------------- LayerNorm (ddof=1), output fp16 ----------------
__global__ __launch_bounds__(256) void ln_h_kernel(
    const float* __restrict__ x, const float* __restrict__ mean_scale,
    const float* __restrict__ std_scale, __half* __restrict__ out)
{
    int row = blockIdx.x;
    int t = threadIdx.x;
    const float4* xr = (const float4*)(x + (size_t)row*DMODEL);
    float4 v = xr[t];

    __shared__ float red[8];
    float s = v.x + v.y + v.z + v.w;
    #pragma unroll
    for (int m = 16; m > 0; m >>= 1) s += __shfl_xor_sync(0xffffffffu, s, m);
    if ((t & 31) == 0) red[t >> 5] = s;
    __syncthreads();
    if (t < 8) {
        float r = red[t];
        #pragma unroll
        for (int m = 4; m > 0; m >>= 1) r += __shfl_xor_sync(0xffu, r, m);
        if (t == 0) red[0] = r;
    }
    __syncthreads();
    float mean = red[0] * (1.0f / DMODEL);
    float dx = v.x - mean, dy = v.y - mean, dz = v.z - mean, dw = v.w - mean;
    float q = dx*dx + dy*dy + dz*dz + dw*dw;
    __syncthreads();
    #pragma unroll
    for (int m = 16; m > 0; m >>= 1) q += __shfl_xor_sync(0xffffffffu, q, m);
    if ((t & 31) == 0) red[t >> 5] = q;
    __syncthreads();
    if (t < 8) {
        float r = red[t];
        #pragma unroll
        for (int m = 4; m > 0; m >>= 1) r += __shfl_xor_sync(0xffu, r, m);
        if (t == 0) red[0] = r;
    }
    __syncthreads();
    float var = red[0] * (1.0f / (DMODEL - 1));
    float rstd = rsqrtf(var + LN_EPS);

    float4 msv = ((const float4*)mean_scale)[t];
    float4 ssv = ((const float4*)std_scale)[t];
    __half2* o = (__half2*)(out + (size_t)row*DMODEL) + 2*t;
    o[0] = __floats2half2_rn(dx * rstd * ssv.x + msv.x, dy * rstd * ssv.y + msv.y);
    o[1] = __floats2half2_rn(dz * rstd * ssv.z + msv.z, dw * rstd * ssv.w + msv.w);
}

// ---------------- FP16 mma.sync GEMM (proven layout) ----------------
#define EPI_HALF 0   // write half2 * esc to Ch
#define EPI_GELU 1   // write gelu as half to Ch
#define EPI_ADD  2   // write fp32 + R to Cf

#define TSTR 36
#define TILE_FLOATS (128*TSTR)
#define GH_SMEM (4 * TILE_FLOATS * 4)   // 73728 B

__device__ __forceinline__ void fill_h(
    const __half* __restrict__ Ag, const __half* __restrict__ Wg, int K, int k0,
    float* __restrict__ As, float* __restrict__ Bs, int t)
{
    #pragma unroll
    for (int i = 0; i < 4; i++) {
        int lin = t + i * 256;
        int row = lin >> 3, u = lin & 7;
        cp16(As + row*TSTR + u*4, Ag + (size_t)row * K + k0 + u*8);
        cp16(Bs + row*TSTR + u*4, Wg + (size_t)row * K + k0 + u*8);
    }
}

template<int EPI>
__device__ __forceinline__ void gemmh_body(
    const __half* __restrict__ A, const __half* __restrict__ W,
    const float* __restrict__ R, float* __restrict__ Cf, __half* __restrict__ Ch,
    int N, int K, float esc)
{
    extern __shared__ __align__(16) float smem[];
    float* As = smem;
    float* Bs = smem + 2*TILE_FLOATS;

    int t = threadIdx.x;
    int warp = t >> 5, lane = t & 31;
    int wm = warp & 1, wn = warp >> 1;
    int g = lane >> 2, q = lane & 3;

    const __half* Ag = A + (size_t)(blockIdx.y * 128) * K;
    const __half* Wg = W + (size_t)(blockIdx.x * 128) * K;

    float acc[4][4][4];
    #pragma unroll
    for (int i = 0; i < 4; i++)
        #pragma unroll
        for (int j = 0; j < 4; j++)
            #pragma unroll
            for (int c = 0; c < 4; c++) acc[i][j][c] = 0.0f;

    int nk = K >> 6;

    fill_h(Ag, Wg, K, 0, As, Bs, t);
    cp_commit();

    for (int kt = 0; kt < nk; kt++) {
        int buf = kt & 1;
        if (kt + 1 < nk) {
            int nbuf = (kt + 1) & 1;
            fill_h(Ag, Wg, K, (kt + 1) << 6,
                   As + nbuf*TILE_FLOATS, Bs + nbuf*TILE_FLOATS, t);
            cp_commit();
            cp_wait<1>();
        } else {
            cp_wait<0>();
        }
        __syncthreads();

        const float* Abs = As + buf * TILE_FLOATS;
        const float* Bbs = Bs + buf * TILE_FLOATS;
        #pragma unroll
        for (int ks = 0; ks < 4; ks++) {
            int kb = ks * 8;
            uint32_t af[4][4], bf[4][2];
            #pragma unroll
            for (int mt = 0; mt < 4; mt++) {
                int m = wm*64 + mt*16 + g;
                af[mt][0] = __float_as_uint(Abs[m*TSTR + kb + q]);
                af[mt][1] = __float_as_uint(Abs[(m+8)*TSTR + kb + q]);
                af[mt][2] = __float_as_uint(Abs[m*TSTR + kb + q + 4]);
                af[mt][3] = __float_as_uint(Abs[(m+8)*TSTR + kb + q + 4]);
            }
            #pragma unroll
            for (int nt = 0; nt < 4; nt++) {
                int n = wn*32 + nt*8 + g;
                bf[nt][0] = __float_as_uint(Bbs[n*TSTR + kb + q]);
                bf[nt][1] = __float_as_uint(Bbs[n*TSTR + kb + q + 4]);
            }
            #pragma unroll
            for (int mt = 0; mt < 4; mt++)
                #pragma unroll
                for (int nt = 0; nt < 4; nt++)
                    mma_f16(acc[mt][nt][0], acc[mt][nt][1], acc[mt][nt][2], acc[mt][nt][3],
                            af[mt][0], af[mt][1], af[mt][2], af[mt][3],
                            bf[nt][0], bf[nt][1]);
        }
        __syncthreads();
    }

    int browb = blockIdx.y * 128 + wm * 64;
    int bcolb = blockIdx.x * 128 + wn * 32;
    #pragma unroll
    for (int mt = 0; mt < 4; mt++) {
        #pragma unroll
        for (int nt = 0; nt < 4; nt++) {
            int r0 = browb + mt*16 + g;
            int c0 = bcolb + nt*8 + 2*q;
            #pragma unroll
            for (int half = 0; half < 2; half++) {
                int r = r0 + half*8;
                float vx = acc[mt][nt][half*2 + 0];
                float vy = acc[mt][nt][half*2 + 1];
                size_t base = (size_t)r * N + c0;
                if (EPI == EPI_HALF) {
                    *(__half2*)(Ch + base) = __floats2half2_rn(vx*esc, vy*esc);
                } else if (EPI == EPI_GELU) {
                    *(__half2*)(Ch + base) =
                        __floats2half2_rn(gelu_exact(vx), gelu_exact(vy));
                } else {
                    float2 rr = *(const float2*)(R + base);
                    float2 o; o.x = vx + rr.x; o.y = vy + rr.y;
                    *(float2*)(Cf + base) = o;
                }
            }
        }
    }
}

template<int EPI>
__global__ __launch_bounds__(256, 2) void gemmh(
    const __half* __restrict__ A, const __half* __restrict__ W,
    const float* __restrict__ R, float* __restrict__ Cf, __half* __restrict__ Ch,
    int N, int K, float esc)
{
    gemmh_body<EPI>(A, W, R, Cf, Ch, N, K, esc);
}

__global__ __launch_bounds__(256, 2) void gemmh_qkv(
    const __half* __restrict__ A,
    const __half* __restrict__ W0, const __half* __restrict__ W1, const __half* __restrict__ W2,
    __half* __restrict__ H0, __half* __restrict__ H1, __half* __restrict__ H2)
{
    const __half* W = (blockIdx.z == 0) ? W0 : (blockIdx.z == 1) ? W1 : W2;
    __half* H = (blockIdx.z == 0) ? H0 : (blockIdx.z == 1) ? H1 : H2;
    float esc = (blockIdx.z == 0) ? 0.125f : 1.0f;   // fold 1/sqrt(hd) into Q
    gemmh_body<EPI_HALF>(A, W, nullptr, nullptr, H, DMODEL, DMODEL, esc);
}

// ---------------- FP16 flash attention, causal ----------------
// Q pre-scaled by 1/8. Tiles 64x64, 4 warps, warp w owns rows 16w..16w+15.
// smem float-slot stride per row: AST=36 floats (72 halves, 144B).
// Each tile row = 64 halves = 128B = 8 x 16B chunks -> 512 chunks per tile.
#define AST 36
#define ATT_SMEM (6 * 64 * AST * 4)   // 55296 B

__global__ __launch_bounds__(128) void attn_h(
    const __half* __restrict__ Q, const __half* __restrict__ K,
    const __half* __restrict__ V, __half* __restrict__ O)
{
    extern __shared__ __align__(16) float sm[];
    float* Qs = sm;                  // [64][36]
    float* Ks = sm + 64*AST;         // [2][64][36]
    float* Vs = sm + 3*64*AST;       // [2][64][36]
    float* Ps = sm + 5*64*AST;       // [64][36]

    int qt = blockIdx.x, h = blockIdx.y, b = blockIdx.z;
    int t = threadIdx.x;
    int warp = t >> 5, lane = t & 31;
    int g = lane >> 2, q = lane & 3;

    const __half* Qb = Q + ((size_t)b*SEQ + (size_t)qt*64) * DMODEL + h*HD;
    const __half* Kb = K + (size_t)b*SEQ*DMODEL + h*HD;
    const __half* Vb = V + (size_t)b*SEQ*DMODEL + h*HD;

    // prologue: Q tile + K/V tile 0 (one cp.async group). 512 chunks per tile.
    #pragma unroll
    for (int i = 0; i < 4; i++) {
        int lin = t + i*128;                 // 0..511
        int r = lin >> 3, u = lin & 7;       // 8 x 16B chunks per 64-half row
        cp16(Qs + r*AST + u*4, Qb + (size_t)r*DMODEL + u*8);
        cp16(Ks + r*AST + u*4, Kb + (size_t)r*DMODEL + u*8);
        cp16(Vs + r*AST + u*4, Vb + (size_t)r*DMODEL + u*8);
    }
    cp_commit();

    float acc[8][4];
    #pragma unroll
    for (int nt = 0; nt < 8; nt++)
        #pragma unroll
        for (int c = 0; c < 4; c++) acc[nt][c] = 0.0f;
    float m0 = -1e30f, m1 = -1e30f, l0 = 0.0f, l1 = 0.0f;

    int r0 = 16*warp + g;
    int r1 = r0 + 8;
    int grp = lane >> 3, li = lane & 7;      // ldmatrix address lanes

    for (int kt = 0; kt <= qt; kt++) {
        int buf = kt & 1;
        if (kt < qt) {
            int nbuf = (kt + 1) & 1;
            const __half* Kt = Kb + (size_t)(kt+1) * 64 * DMODEL;
            const __half* Vt = Vb + (size_t)(kt+1) * 64 * DMODEL;
            float* Kd = Ks + nbuf*64*AST;
            float* Vd = Vs + nbuf*64*AST;
            #pragma unroll
            for (int i = 0; i < 4; i++) {
                int lin = t + i*128;
                int r = lin >> 3, u = lin & 7;
                cp16(Kd + r*AST + u*4, Kt + (size_t)r*DMODEL + u*8);
                cp16(Vd + r*AST + u*4, Vt + (size_t)r*DMODEL + u*8);
            }
            cp_commit();
            cp_wait<1>();
        } else {
            cp_wait<0>();
        }
        __syncthreads();

        const float* Kbuf = Ks + buf*64*AST;
        const float* Vbuf = Vs + buf*64*AST;

        // ---- scores: S = Q K^T (fp16 MMA, 4 k-steps of 16 halves) ----
        float sc[8][4];
        #pragma unroll
        for (int nt = 0; nt < 8; nt++)
            #pragma unroll
            for (int c = 0; c < 4; c++) sc[nt][c] = 0.0f;

        #pragma unroll
        for (int ks = 0; ks < 4; ks++) {
            int kb = ks * 8;
            uint32_t a0 = __float_as_uint(Qs[r0*AST + kb + q]);
            uint32_t a1 = __float_as_uint(Qs[r1*AST + kb + q]);
            uint32_t a2 = __float_as_uint(Qs[r0*AST + kb + q + 4]);
            uint32_t a3 = __float_as_uint(Qs[r1*AST + kb + q + 4]);
            #pragma unroll
            for (int nt = 0; nt < 8; nt++) {
                uint32_t b0 = __float_as_uint(Kbuf[(8*nt+g)*AST + kb + q]);
                uint32_t b1 = __float_as_uint(Kbuf[(8*nt+g)*AST + kb + q + 4]);
                mma_f16(sc[nt][0], sc[nt][1], sc[nt][2], sc[nt][3],
                        a0, a1, a2, a3, b0, b1);
            }
        }

        if (kt == qt) {
            #pragma unroll
            for (int nt = 0; nt < 8; nt++) {
                int col0 = 8*nt + 2*q;
                if (col0     > r0) sc[nt][0] = -1e30f;
                if (col0 + 1 > r0) sc[nt][1] = -1e30f;
                if (col0     > r1) sc[nt][2] = -1e30f;
                if (col0 + 1 > r1) sc[nt][3] = -1e30f;
            }
        }

        // ---- online softmax ----
        float tm0 = -1e30f, tm1 = -1e30f;
        #pragma unroll
        for (int nt = 0; nt < 8; nt++) {
            tm0 = fmaxf(tm0, fmaxf(sc[nt][0], sc[nt][1]));
            tm1 = fmaxf(tm1, fmaxf(sc[nt][2], sc[nt][3]));
        }
        tm0 = fmaxf(tm0, __shfl_xor_sync(0xffffffffu, tm0, 1));
        tm0 = fmaxf(tm0, __shfl_xor_sync(0xffffffffu, tm0, 2));
        tm1 = fmaxf(tm1, __shfl_xor_sync(0xffffffffu, tm1, 1));
        tm1 = fmaxf(tm1, __shfl_xor_sync(0xffffffffu, tm1, 2));

        float m0n = fmaxf(m0, tm0);
        float m1n = fmaxf(m1, tm1);
        float corr0 = __expf(m0 - m0n);
        float corr1 = __expf(m1 - m1n);

        __half* Ph = (__half*)Ps;
        float sum0 = 0.0f, sum1 = 0.0f;
        #pragma unroll
        for (int nt = 0; nt < 8; nt++) {
            float p0 = __expf(sc[nt][0] - m0n);
            float p1 = __expf(sc[nt][1] - m0n);
            float p2 = __expf(sc[nt][2] - m1n);
            float p3 = __expf(sc[nt][3] - m1n);
            sum0 += p0 + p1;
            sum1 += p2 + p3;
            *(__half2*)&Ph[r0*72 + 8*nt + 2*q] = __floats2half2_rn(p0, p1);
            *(__half2*)&Ph[r1*72 + 8*nt + 2*q] = __floats2half2_rn(p2, p3);
        }
        sum0 += __shfl_xor_sync(0xffffffffu, sum0, 1);
        sum0 += __shfl_xor_sync(0xffffffffu, sum0, 2);
        sum1 += __shfl_xor_sync(0xffffffffu, sum1, 1);
        sum1 += __shfl_xor_sync(0xffffffffu, sum1, 2);

        l0 = l0 * corr0 + sum0;
        l1 = l1 * corr1 + sum1;
        m0 = m0n; m1 = m1n;
        #pragma unroll
        for (int nt = 0; nt < 8; nt++) {
            acc[nt][0] *= corr0; acc[nt][1] *= corr0;
            acc[nt][2] *= corr1; acc[nt][3] *= corr1;
        }
        __syncwarp();   // P rows are warp-private; order stores before frag loads

        // ---- PV: acc += P @ V (fp16 MMA; V fragments via ldmatrix.trans) ----
        const __half* Vh = (const __half*)Vbuf;
        #pragma unroll
        for (int ks = 0; ks < 4; ks++) {
            int kb = ks * 8;
            uint32_t a0 = __float_as_uint(Ps[r0*AST + kb + q]);
            uint32_t a1 = __float_as_uint(Ps[r1*AST + kb + q]);
            uint32_t a2 = __float_as_uint(Ps[r0*AST + kb + q + 4]);
            uint32_t a3 = __float_as_uint(Ps[r1*AST + kb + q + 4]);
            #pragma unroll
            for (int np = 0; np < 4; np++) {
                // x4.trans: m0/m1 = b0/b1 of col-tile 2np, m2/m3 = of 2np+1
                const __half* ap = Vh + (size_t)(ks*16 + ((grp & 1) << 3) + li) * 72
                                      + ((2*np + (grp >> 1)) << 3);
                uint32_t sa = (uint32_t)__cvta_generic_to_shared(ap);
                uint32_t v0, v1, v2, v3;
                asm volatile(
                    "ldmatrix.sync.aligned.m8n8.x4.trans.shared.b16 {%0,%1,%2,%3}, [%4];"
                    : "=r"(v0), "=r"(v1), "=r"(v2), "=r"(v3) : "r"(sa));
                mma_f16(acc[2*np+0][0], acc[2*np+0][1], acc[2*np+0][2], acc[2*np+0][3],
                        a0, a1, a2, a3, v0, v1);
                mma_f16(acc[2*np+1][0], acc[2*np+1][1], acc[2*np+1][2], acc[2*np+1][3],
                        a0, a1, a2, a3, v2, v3);
            }
        }
        __syncthreads();
    }

    float inv0 = 1.0f / l0;
    float inv1 = 1.0f / l1;
    __half* Ob = O + ((size_t)b*SEQ + (size_t)qt*64) * DMODEL + h*HD;
    #pragma unroll
    for (int nt = 0; nt < 8; nt++) {
        int col = 8*nt + 2*q;
        *(__half2*)(Ob + (size_t)r0 * DMODEL + col) =
            __floats2half2_rn(acc[nt][0]*inv0, acc[nt][1]*inv0);
        *(__half2*)(Ob + (size_t)r1 * DMODEL + col) =
            __floats2half2_rn(acc[nt][2]*inv1, acc[nt][3]*inv1);
    }
}

// ---------------- launch ----------------
extern "C" void kernel_launch(void* const* d_in, const int* in_sizes, int n_in,
                              void* d_out, int out_size)
{
    const float* x    = (const float*)d_in[0];
    const float* Wq   = (const float*)d_in[1];
    const float* Wk   = (const float*)d_in[2];
    const float* Wv   = (const float*)d_in[3];
    const float* Wo   = (const float*)d_in[4];
    const float* Wup  = (const float*)d_in[5];
    const float* Wdn  = (const float*)d_in[6];
    const float* ln1m = (const float*)d_in[7];
    const float* ln1s = (const float*)d_in[8];
    const float* ln2m = (const float*)d_in[9];
    const float* ln2s = (const float*)d_in[10];
    float* out = (float*)d_out;

    float *b4;
    __half *hln1, *hq, *hk, *hv, *hO, *hln2, *hmid;
    __half *hwq, *hwk, *hwv, *hwo, *hwup, *hwdn;
    cudaGetSymbolAddress((void**)&b4, g_buf4);
    cudaGetSymbolAddress((void**)&hln1, g_hln1);
    cudaGetSymbolAddress((void**)&hq,   g_hq);
    cudaGetSymbolAddress((void**)&hk,   g_hk);
    cudaGetSymbolAddress((void**)&hv,   g_hv);
    cudaGetSymbolAddress((void**)&hO,   g_hO);
    cudaGetSymbolAddress((void**)&hln2, g_hln2);
    cudaGetSymbolAddress((void**)&hmid, g_hmid);
    cudaGetSymbolAddress((void**)&hwq,  g_hwq);
    cudaGetSymbolAddress((void**)&hwk,  g_hwk);
    cudaGetSymbolAddress((void**)&hwv,  g_hwv);
    cudaGetSymbolAddress((void**)&hwo,  g_hwo);
    cudaGetSymbolAddress((void**)&hwup, g_hwup);
    cudaGetSymbolAddress((void**)&hwdn, g_hwdn);

    cudaFuncSetAttribute(gemmh<EPI_HALF>, cudaFuncAttributeMaxDynamicSharedMemorySize, GH_SMEM);
    cudaFuncSetAttribute(gemmh<EPI_GELU>, cudaFuncAttributeMaxDynamicSharedMemorySize, GH_SMEM);
    cudaFuncSetAttribute(gemmh<EPI_ADD>,  cudaFuncAttributeMaxDynamicSharedMemorySize, GH_SMEM);
    cudaFuncSetAttribute(gemmh_qkv,       cudaFuncAttributeMaxDynamicSharedMemorySize, GH_SMEM);
    cudaFuncSetAttribute(attn_h,          cudaFuncAttributeMaxDynamicSharedMemorySize, ATT_SMEM);

    // merged weight conversion (single launch)
    convall_kernel<<<12288, 256>>>(Wq, Wk, Wv, Wo, Wup, Wdn,
                                   hwq, hwk, hwv, hwo, hwup, hwdn);

    dim3 gproj(DMODEL/128, MROWS/128);      // (8, 32)
    dim3 gqkv (DMODEL/128, MROWS/128, 3);
    dim3 gup  (DFF/128,    MROWS/128);      // (32, 32)

    // LN1 -> fp16
    ln_h_kernel<<<MROWS, 256>>>(x, ln1m, ln1s, hln1);
    // fused QKV -> half (Q pre-scaled by 1/8)
    gemmh_qkv<<<gqkv, 256, GH_SMEM>>>(hln1, hwq, hwk, hwv, hq, hk, hv);
    // fp16 flash attention -> half O
    attn_h<<<dim3(SEQ/64, NH, BDIM), 128, ATT_SMEM>>>(hq, hk, hv, hO);
    // out proj + residual -> y1 (fp32)
    gemmh<EPI_ADD><<<gproj, 256, GH_SMEM>>>(hO, hwo, x, b4, nullptr, DMODEL, DMODEL, 1.0f);
    // LN2 -> fp16
    ln_h_kernel<<<MROWS, 256>>>(b4, ln2m, ln2s, hln2);
    // MLP up + GELU -> half mid
    gemmh<EPI_GELU><<<gup, 256, GH_SMEM>>>(hln2, hwup, nullptr, nullptr, hmid, DFF, DMODEL, 1.0f);
    // MLP down + residual -> out (fp32)
    gemmh<EPI_ADD><<<gproj, 256, GH_SMEM>>>(hmid, hwdn, b4, out, nullptr, DMODEL, DFF, 1.0f);
}

// round 16
// speedup vs baseline: 3.2283x; 1.0760x over previous
#include <cuda_runtime.h>
#include <cuda_fp16.h>
#include <math.h>
#include <stdint.h>

#define BDIM 2
#define SEQ  2048
#define DMODEL 1024
#define NH   16
#define HD   64
#define MROWS (BDIM*SEQ)     // 4096
#define DFF  4096
#define LN_EPS 1e-9f

// ---------------- scratch ----------------
__device__ float g_buf4[(size_t)MROWS*DMODEL];   // y1 = x + attn (fp32)
__device__ __half g_hln1[(size_t)MROWS*DMODEL];  // ln1 out
__device__ __half g_hq [(size_t)MROWS*DMODEL];   // Q (half, pre-scaled 1/8)
__device__ __half g_hk [(size_t)MROWS*DMODEL];   // K
__device__ __half g_hv [(size_t)MROWS*DMODEL];   // V
__device__ __half g_hO [(size_t)MROWS*DMODEL];   // attention O
__device__ __half g_hln2[(size_t)MROWS*DMODEL];  // ln2 out
__device__ __half g_hmid[(size_t)MROWS*DFF];     // MLP mid
// half weights
__device__ __half g_hwq[(size_t)DMODEL*DMODEL];
__device__ __half g_hwk[(size_t)DMODEL*DMODEL];
__device__ __half g_hwv[(size_t)DMODEL*DMODEL];
__device__ __half g_hwo[(size_t)DMODEL*DMODEL];
__device__ __half g_hwup[(size_t)DFF*DMODEL];
__device__ __half g_hwdn[(size_t)DMODEL*DFF];

// ---------------- helpers ----------------
__device__ __forceinline__ void cp16(void* s, const void* g) {
    uint32_t sa = (uint32_t)__cvta_generic_to_shared(s);
    asm volatile("cp.async.cg.shared.global [%0], [%1], 16;" :: "r"(sa), "l"(g));
}
__device__ __forceinline__ void cp_commit() {
    asm volatile("cp.async.commit_group;");
}
template<int NGRP> __device__ __forceinline__ void cp_wait() {
    asm volatile("cp.async.wait_group %0;" :: "n"(NGRP));
}
__device__ __forceinline__ float gelu_exact(float v) {
    return 0.5f * v * (1.0f + erff(v * 0.7071067811865476f));
}
__device__ __forceinline__ void mma_f16(
    float& c0, float& c1, float& c2, float& c3,
    uint32_t a0, uint32_t a1, uint32_t a2, uint32_t a3,
    uint32_t b0, uint32_t b1)
{
    asm volatile(
        "mma.sync.aligned.m16n8k16.row.col.f32.f16.f16.f32 "
        "{%0,%1,%2,%3}, {%4,%5,%6,%7}, {%8,%9}, {%0,%1,%2,%3};"
        : "+f"(c0), "+f"(c1), "+f"(c2), "+f"(c3)
        : "r"(a0), "r"(a1), "r"(a2), "r"(a3), "r"(b0), "r"(b1));
}
__device__ __forceinline__ void ldsm_x4(uint32_t& r0, uint32_t& r1, uint32_t& r2, uint32_t& r3,
                                        const void* p)
{
    uint32_t sa = (uint32_t)__cvta_generic_to_shared(p);
    asm volatile("ldmatrix.sync.aligned.m8n8.x4.shared.b16 {%0,%1,%2,%3}, [%4];"
                 : "=r"(r0), "=r"(r1), "=r"(r2), "=r"(r3) : "r"(sa));
}

// ---------------- merged weight conversion fp32 -> fp16 ----------------
__global__ __launch_bounds__(256) void convall_kernel(
    const float* __restrict__ q, const float* __restrict__ k,
    const float* __restrict__ v, const float* __restrict__ o,
    const float* __restrict__ up, const float* __restrict__ dn,
    __half* hq, __half* hk, __half* hv, __half* ho,
    __half* hup, __half* hdn)
{
    int bid = blockIdx.x;
    const float* src; __half* dst; int rel;
    if      (bid < 1024) { src = q;  dst = hq;  rel = bid; }
    else if (bid < 2048) { src = k;  dst = hk;  rel = bid - 1024; }
    else if (bid < 3072) { src = v;  dst = hv;  rel = bid - 2048; }
    else if (bid < 4096) { src = o;  dst = ho;  rel = bid - 3072; }
    else if (bid < 8192) { src = up; dst = hup; rel = bid - 4096; }
    else                 { src = dn; dst = hdn; rel = bid - 8192; }
    size_t i = (size_t)rel * 256 + threadIdx.x;
    float4 vv = ((const float4*)src)[i];
    __half2* outp = (__half2*)dst + 2*i;
    outp[0] = __floats2half2_rn(vv.x, vv.y);
    outp[1] = __floats2half2_rn(vv.z, vv.w);
}

// ---------------- LayerNorm (ddof=1), output fp16 ----------------
__global__ __launch_bounds__(256) void ln_h_kernel(
    const float* __restrict__ x, const float* __restrict__ mean_scale,
    const float* __restrict__ std_scale, __half* __restrict__ out)
{
    int row = blockIdx.x;
    int t = threadIdx.x;
    const float4* xr = (const float4*)(x + (size_t)row*DMODEL);
    float4 v = xr[t];

    __shared__ float red[8];
    float s = v.x + v.y + v.z + v.w;
    #pragma unroll
    for (int m = 16; m > 0; m >>= 1) s += __shfl_xor_sync(0xffffffffu, s, m);
    if ((t & 31) == 0) red[t >> 5] = s;
    __syncthreads();
    if (t < 8) {
        float r = red[t];
        #pragma unroll
        for (int m = 4; m > 0; m >>= 1) r += __shfl_xor_sync(0xffu, r, m);
        if (t == 0) red[0] = r;
    }
    __syncthreads();
    float mean = red[0] * (1.0f / DMODEL);
    float dx = v.x - mean, dy = v.y - mean, dz = v.z - mean, dw = v.w - mean;
    float q = dx*dx + dy*dy + dz*dz + dw*dw;
    __syncthreads();
    #pragma unroll
    for (int m = 16; m > 0; m >>= 1) q += __shfl_xor_sync(0xffffffffu, q, m);
    if ((t & 31) == 0) red[t >> 5] = q;
    __syncthreads();
    if (t < 8) {
        float r = red[t];
        #pragma unroll
        for (int m = 4; m > 0; m >>= 1) r += __shfl_xor_sync(0xffu, r, m);
        if (t == 0) red[0] = r;
    }
    __syncthreads();
    float var = red[0] * (1.0f / (DMODEL - 1));
    float rstd = rsqrtf(var + LN_EPS);

    float4 msv = ((const float4*)mean_scale)[t];
    float4 ssv = ((const float4*)std_scale)[t];
    __half2* o = (__half2*)(out + (size_t)row*DMODEL) + 2*t;
    o[0] = __floats2half2_rn(dx * rstd * ssv.x + msv.x, dy * rstd * ssv.y + msv.y);
    o[1] = __floats2half2_rn(dz * rstd * ssv.z + msv.z, dw * rstd * ssv.w + msv.w);
}

// ---------------- FP16 mma.sync GEMM (stride-36 layout + ldmatrix frags) ----------------
#define EPI_HALF 0   // write half2 * esc to Ch
#define EPI_GELU 1   // write gelu as half to Ch
#define EPI_ADD  2   // write fp32 + R to Cf

#define TSTR 36
#define TILE_FLOATS (128*TSTR)
#define GH_SMEM (4 * TILE_FLOATS * 4)   // 73728 B

__device__ __forceinline__ void fill_h(
    const __half* __restrict__ Ag, const __half* __restrict__ Wg, int K, int k0,
    float* __restrict__ As, float* __restrict__ Bs, int t)
{
    #pragma unroll
    for (int i = 0; i < 4; i++) {
        int lin = t + i * 256;
        int row = lin >> 3, u = lin & 7;
        cp16(As + row*TSTR + u*4, Ag + (size_t)row * K + k0 + u*8);
        cp16(Bs + row*TSTR + u*4, Wg + (size_t)row * K + k0 + u*8);
    }
}

template<int EPI>
__device__ __forceinline__ void gemmh_body(
    const __half* __restrict__ A, const __half* __restrict__ W,
    const float* __restrict__ R, float* __restrict__ Cf, __half* __restrict__ Ch,
    int N, int K, float esc)
{
    extern __shared__ __align__(16) float smem[];
    float* As = smem;
    float* Bs = smem + 2*TILE_FLOATS;

    int t = threadIdx.x;
    int warp = t >> 5, lane = t & 31;
    int wm = warp & 1, wn = warp >> 1;
    int g = lane >> 2, q = lane & 3;

    // ldmatrix per-lane address components
    int a_row = wm*64 + (lane & 15);          // + mt*16
    int a_k4  = (lane >> 4) << 2;             // 0 or 4 float slots
    int b_row = wn*32 + ((lane & 16) >> 1) + (lane & 7);   // + np*16
    int b_k4  = (lane & 8) >> 1;              // 0 or 4 float slots

    const __half* Ag = A + (size_t)(blockIdx.y * 128) * K;
    const __half* Wg = W + (size_t)(blockIdx.x * 128) * K;

    float acc[4][4][4];
    #pragma unroll
    for (int i = 0; i < 4; i++)
        #pragma unroll
        for (int j = 0; j < 4; j++)
            #pragma unroll
            for (int c = 0; c < 4; c++) acc[i][j][c] = 0.0f;

    int nk = K >> 6;

    fill_h(Ag, Wg, K, 0, As, Bs, t);
    cp_commit();

    for (int kt = 0; kt < nk; kt++) {
        int buf = kt & 1;
        if (kt + 1 < nk) {
            int nbuf = (kt + 1) & 1;
            fill_h(Ag, Wg, K, (kt + 1) << 6,
                   As + nbuf*TILE_FLOATS, Bs + nbuf*TILE_FLOATS, t);
            cp_commit();
            cp_wait<1>();
        } else {
            cp_wait<0>();
        }
        __syncthreads();

        const float* Abs = As + buf * TILE_FLOATS;
        const float* Bbs = Bs + buf * TILE_FLOATS;
        #pragma unroll
        for (int ks = 0; ks < 4; ks++) {
            int kb = ks * 8;
            uint32_t af[4][4], bf[4][2];
            #pragma unroll
            for (int mt = 0; mt < 4; mt++)
                ldsm_x4(af[mt][0], af[mt][1], af[mt][2], af[mt][3],
                        Abs + (a_row + mt*16)*TSTR + kb + a_k4);
            #pragma unroll
            for (int np = 0; np < 2; np++)
                ldsm_x4(bf[2*np][0], bf[2*np][1], bf[2*np+1][0], bf[2*np+1][1],
                        Bbs + (b_row + np*16)*TSTR + kb + b_k4);
            #pragma unroll
            for (int mt = 0; mt < 4; mt++)
                #pragma unroll
                for (int nt = 0; nt < 4; nt++)
                    mma_f16(acc[mt][nt][0], acc[mt][nt][1], acc[mt][nt][2], acc[mt][nt][3],
                            af[mt][0], af[mt][1], af[mt][2], af[mt][3],
                            bf[nt][0], bf[nt][1]);
        }
        __syncthreads();
    }

    int browb = blockIdx.y * 128 + wm * 64;
    int bcolb = blockIdx.x * 128 + wn * 32;
    #pragma unroll
    for (int mt = 0; mt < 4; mt++) {
        #pragma unroll
        for (int nt = 0; nt < 4; nt++) {
            int r0 = browb + mt*16 + g;
            int c0 = bcolb + nt*8 + 2*q;
            #pragma unroll
            for (int half = 0; half < 2; half++) {
                int r = r0 + half*8;
                float vx = acc[mt][nt][half*2 + 0];
                float vy = acc[mt][nt][half*2 + 1];
                size_t base = (size_t)r * N + c0;
                if (EPI == EPI_HALF) {
                    *(__half2*)(Ch + base) = __floats2half2_rn(vx*esc, vy*esc);
                } else if (EPI == EPI_GELU) {
                    *(__half2*)(Ch + base) =
                        __floats2half2_rn(gelu_exact(vx), gelu_exact(vy));
                } else {
                    float2 rr = *(const float2*)(R + base);
                    float2 o; o.x = vx + rr.x; o.y = vy + rr.y;
                    *(float2*)(Cf + base) = o;
                }
            }
        }
    }
}

template<int EPI>
__global__ __launch_bounds__(256, 2) void gemmh(
    const __half* __restrict__ A, const __half* __restrict__ W,
    const float* __restrict__ R, float* __restrict__ Cf, __half* __restrict__ Ch,
    int N, int K, float esc)
{
    gemmh_body<EPI>(A, W, R, Cf, Ch, N, K, esc);
}

__global__ __launch_bounds__(256, 2) void gemmh_qkv(
    const __half* __restrict__ A,
    const __half* __restrict__ W0, const __half* __restrict__ W1, const __half* __restrict__ W2,
    __half* __restrict__ H0, __half* __restrict__ H1, __half* __restrict__ H2)
{
    const __half* W = (blockIdx.z == 0) ? W0 : (blockIdx.z == 1) ? W1 : W2;
    __half* H = (blockIdx.z == 0) ? H0 : (blockIdx.z == 1) ? H1 : H2;
    float esc = (blockIdx.z == 0) ? 0.125f : 1.0f;   // fold 1/sqrt(hd) into Q
    gemmh_body<EPI_HALF>(A, W, nullptr, nullptr, H, DMODEL, DMODEL, esc);
}

// ---------------- FP16 flash attention, causal, 128 q-rows per CTA ----------------
// 256 threads = 8 warps; warp w owns rows 16w..16w+15 of the 128-row q-block.
// K/V tiles (64 rows) shared across all 8 warps -> fill traffic halved per q-row.
#define AST 36
#define ATT_SMEM ((128*AST + 4*64*AST + 128*AST) * 4)   // 73728 B

__global__ __launch_bounds__(256, 2) void attn_h(
    const __half* __restrict__ Q, const __half* __restrict__ K,
    const __half* __restrict__ V, __half* __restrict__ O)
{
    extern __shared__ __align__(16) float sm[];
    float* Qs = sm;                    // [128][36]
    float* Ks = sm + 128*AST;          // [2][64][36]
    float* Vs = sm + 128*AST + 2*64*AST;  // [2][64][36]
    float* Ps = sm + 128*AST + 4*64*AST;  // [128][36]

    int qb = blockIdx.x, h = blockIdx.y, b = blockIdx.z;
    int t = threadIdx.x;
    int warp = t >> 5, lane = t & 31;
    int g = lane >> 2, q = lane & 3;

    const __half* Qb = Q + ((size_t)b*SEQ + (size_t)qb*128) * DMODEL + h*HD;
    const __half* Kb = K + (size_t)b*SEQ*DMODEL + h*HD;
    const __half* Vb = V + (size_t)b*SEQ*DMODEL + h*HD;

    // prologue: Q (128 rows = 1024 chunks) + K/V tile 0 (512 chunks each)
    #pragma unroll
    for (int i = 0; i < 4; i++) {
        int lin = t + i*256;                 // 0..1023
        int r = lin >> 3, u = lin & 7;
        cp16(Qs + r*AST + u*4, Qb + (size_t)r*DMODEL + u*8);
    }
    #pragma unroll
    for (int i = 0; i < 2; i++) {
        int lin = t + i*256;                 // 0..511
        int r = lin >> 3, u = lin & 7;
        cp16(Ks + r*AST + u*4, Kb + (size_t)r*DMODEL + u*8);
        cp16(Vs + r*AST + u*4, Vb + (size_t)r*DMODEL + u*8);
    }
    cp_commit();

    float acc[8][4];
    #pragma unroll
    for (int nt = 0; nt < 8; nt++)
        #pragma unroll
        for (int c = 0; c < 4; c++) acc[nt][c] = 0.0f;
    float m0 = -1e30f, m1 = -1e30f, l0 = 0.0f, l1 = 0.0f;

    int r0 = 16*warp + g;                // local q row (0..127)
    int r1 = r0 + 8;
    int wbase = qb*128 + 16*warp;        // warp's first global q row

    // ldmatrix per-lane address components (A-style for Q/P, B-style for K)
    int qa_row = 16*warp + (lane & 15);
    int qa_k4  = (lane >> 4) << 2;
    int kb_row = ((lane & 16) >> 1) + (lane & 7);   // + np*16
    int kb_k4  = (lane & 8) >> 1;
    int grp = lane >> 3, li = lane & 7;  // V trans-ldmatrix lanes

    int nkt = 2*qb + 2;
    for (int kt = 0; kt < nkt; kt++) {
        int buf = kt & 1;
        if (kt + 1 < nkt) {
            int nbuf = (kt + 1) & 1;
            const __half* Kt = Kb + (size_t)(kt+1) * 64 * DMODEL;
            const __half* Vt = Vb + (size_t)(kt+1) * 64 * DMODEL;
            float* Kd = Ks + nbuf*64*AST;
            float* Vd = Vs + nbuf*64*AST;
            #pragma unroll
            for (int i = 0; i < 2; i++) {
                int lin = t + i*256;
                int r = lin >> 3, u = lin & 7;
                cp16(Kd + r*AST + u*4, Kt + (size_t)r*DMODEL + u*8);
                cp16(Vd + r*AST + u*4, Vt + (size_t)r*DMODEL + u*8);
            }
            cp_commit();
            cp_wait<1>();
        } else {
            cp_wait<0>();
        }
        __syncthreads();

        bool active = (kt*64 <= wbase + 15);
        if (active) {
            const float* Kbuf = Ks + buf*64*AST;
            const float* Vbuf = Vs + buf*64*AST;

            // ---- scores: S = Q K^T ----
            float sc[8][4];
            #pragma unroll
            for (int nt = 0; nt < 8; nt++)
                #pragma unroll
                for (int c = 0; c < 4; c++) sc[nt][c] = 0.0f;

            #pragma unroll
            for (int ks = 0; ks < 4; ks++) {
                int kb = ks * 8;
                uint32_t a0, a1, a2, a3;
                ldsm_x4(a0, a1, a2, a3, Qs + qa_row*AST + kb + qa_k4);
                uint32_t bfv[8][2];
                #pragma unroll
                for (int np = 0; np < 4; np++)
                    ldsm_x4(bfv[2*np][0], bfv[2*np][1], bfv[2*np+1][0], bfv[2*np+1][1],
                            Kbuf + (kb_row + np*16)*AST + kb + kb_k4);
                #pragma unroll
                for (int nt = 0; nt < 8; nt++)
                    mma_f16(sc[nt][0], sc[nt][1], sc[nt][2], sc[nt][3],
                            a0, a1, a2, a3, bfv[nt][0], bfv[nt][1]);
            }

            // causal mask (needed only near the diagonal)
            if (kt*64 + 63 > wbase) {
                int diff0 = wbase + g - kt*64;
                int diff1 = diff0 + 8;
                #pragma unroll
                for (int nt = 0; nt < 8; nt++) {
                    int col0 = 8*nt + 2*q;
                    if (col0     > diff0) sc[nt][0] = -1e30f;
                    if (col0 + 1 > diff0) sc[nt][1] = -1e30f;
                    if (col0     > diff1) sc[nt][2] = -1e30f;
                    if (col0 + 1 > diff1) sc[nt][3] = -1e30f;
                }
            }

            // ---- online softmax ----
            float tm0 = -1e30f, tm1 = -1e30f;
            #pragma unroll
            for (int nt = 0; nt < 8; nt++) {
                tm0 = fmaxf(tm0, fmaxf(sc[nt][0], sc[nt][1]));
                tm1 = fmaxf(tm1, fmaxf(sc[nt][2], sc[nt][3]));
            }
            tm0 = fmaxf(tm0, __shfl_xor_sync(0xffffffffu, tm0, 1));
            tm0 = fmaxf(tm0, __shfl_xor_sync(0xffffffffu, tm0, 2));
            tm1 = fmaxf(tm1, __shfl_xor_sync(0xffffffffu, tm1, 1));
            tm1 = fmaxf(tm1, __shfl_xor_sync(0xffffffffu, tm1, 2));

            float m0n = fmaxf(m0, tm0);
            float m1n = fmaxf(m1, tm1);
            float corr0 = __expf(m0 - m0n);
            float corr1 = __expf(m1 - m1n);

            __half* Ph = (__half*)Ps;
            float sum0 = 0.0f, sum1 = 0.0f;
            #pragma unroll
            for (int nt = 0; nt < 8; nt++) {
                float p0 = __expf(sc[nt][0] - m0n);
                float p1 = __expf(sc[nt][1] - m0n);
                float p2 = __expf(sc[nt][2] - m1n);
                float p3 = __expf(sc[nt][3] - m1n);
                sum0 += p0 + p1;
                sum1 += p2 + p3;
                *(__half2*)&Ph[r0*72 + 8*nt + 2*q] = __floats2half2_rn(p0, p1);
                *(__half2*)&Ph[r1*72 + 8*nt + 2*q] = __floats2half2_rn(p2, p3);
            }
            sum0 += __shfl_xor_sync(0xffffffffu, sum0, 1);
            sum0 += __shfl_xor_sync(0xffffffffu, sum0, 2);
            sum1 += __shfl_xor_sync(0xffffffffu, sum1, 1);
            sum1 += __shfl_xor_sync(0xffffffffu, sum1, 2);

            l0 = l0 * corr0 + sum0;
            l1 = l1 * corr1 + sum1;
            m0 = m0n; m1 = m1n;
            #pragma unroll
            for (int nt = 0; nt < 8; nt++) {
                acc[nt][0] *= corr0; acc[nt][1] *= corr0;
                acc[nt][2] *= corr1; acc[nt][3] *= corr1;
            }
            __syncwarp();   // P rows are warp-private

            // ---- PV: acc += P @ V ----
            const __half* Vh = (const __half*)Vbuf;
            #pragma unroll
            for (int ks = 0; ks < 4; ks++) {
                int kb = ks * 8;
                uint32_t a0, a1, a2, a3;
                ldsm_x4(a0, a1, a2, a3, Ps + qa_row*AST + kb + qa_k4);
                #pragma unroll
                for (int np = 0; np < 4; np++) {
                    const __half* ap = Vh + (size_t)(ks*16 + ((grp & 1) << 3) + li) * 72
                                          + ((2*np + (grp >> 1)) << 3);
                    uint32_t sa = (uint32_t)__cvta_generic_to_shared(ap);
                    uint32_t v0, v1, v2, v3;
                    asm volatile(
                        "ldmatrix.sync.aligned.m8n8.x4.trans.shared.b16 {%0,%1,%2,%3}, [%4];"
                        : "=r"(v0), "=r"(v1), "=r"(v2), "=r"(v3) : "r"(sa));
                    mma_f16(acc[2*np+0][0], acc[2*np+0][1], acc[2*np+0][2], acc[2*np+0][3],
                            a0, a1, a2, a3, v0, v1);
                    mma_f16(acc[2*np+1][0], acc[2*np+1][1], acc[2*np+1][2], acc[2*np+1][3],
                            a0, a1, a2, a3, v2, v3);
                }
            }
        }
        __syncthreads();
    }

    float inv0 = 1.0f / l0;
    float inv1 = 1.0f / l1;
    __half* Ob = O + ((size_t)b*SEQ + (size_t)qb*128) * DMODEL + h*HD;
    #pragma unroll
    for (int nt = 0; nt < 8; nt++) {
        int col = 8*nt + 2*q;
        *(__half2*)(Ob + (size_t)r0 * DMODEL + col) =
            __floats2half2_rn(acc[nt][0]*inv0, acc[nt][1]*inv0);
        *(__half2*)(Ob + (size_t)r1 * DMODEL + col) =
            __floats2half2_rn(acc[nt][2]*inv1, acc[nt][3]*inv1);
    }
}

// ---------------- launch ----------------
extern "C" void kernel_launch(void* const* d_in, const int* in_sizes, int n_in,
                              void* d_out, int out_size)
{
    const float* x    = (const float*)d_in[0];
    const float* Wq   = (const float*)d_in[1];
    const float* Wk   = (const float*)d_in[2];
    const float* Wv   = (const float*)d_in[3];
    const float* Wo   = (const float*)d_in[4];
    const float* Wup  = (const float*)d_in[5];
    const float* Wdn  = (const float*)d_in[6];
    const float* ln1m = (const float*)d_in[7];
    const float* ln1s = (const float*)d_in[8];
    const float* ln2m = (const float*)d_in[9];
    const float* ln2s = (const float*)d_in[10];
    float* out = (float*)d_out;

    float *b4;
    __half *hln1, *hq, *hk, *hv, *hO, *hln2, *hmid;
    __half *hwq, *hwk, *hwv, *hwo, *hwup, *hwdn;
    cudaGetSymbolAddress((void**)&b4, g_buf4);
    cudaGetSymbolAddress((void**)&hln1, g_hln1);
    cudaGetSymbolAddress((void**)&hq,   g_hq);
    cudaGetSymbolAddress((void**)&hk,   g_hk);
    cudaGetSymbolAddress((void**)&hv,   g_hv);
    cudaGetSymbolAddress((void**)&hO,   g_hO);
    cudaGetSymbolAddress((void**)&hln2, g_hln2);
    cudaGetSymbolAddress((void**)&hmid, g_hmid);
    cudaGetSymbolAddress((void**)&hwq,  g_hwq);
    cudaGetSymbolAddress((void**)&hwk,  g_hwk);
    cudaGetSymbolAddress((void**)&hwv,  g_hwv);
    cudaGetSymbolAddress((void**)&hwo,  g_hwo);
    cudaGetSymbolAddress((void**)&hwup, g_hwup);
    cudaGetSymbolAddress((void**)&hwdn, g_hwdn);

    cudaFuncSetAttribute(gemmh<EPI_HALF>, cudaFuncAttributeMaxDynamicSharedMemorySize, GH_SMEM);
    cudaFuncSetAttribute(gemmh<EPI_GELU>, cudaFuncAttributeMaxDynamicSharedMemorySize, GH_SMEM);
    cudaFuncSetAttribute(gemmh<EPI_ADD>,  cudaFuncAttributeMaxDynamicSharedMemorySize, GH_SMEM);
    cudaFuncSetAttribute(gemmh_qkv,       cudaFuncAttributeMaxDynamicSharedMemorySize, GH_SMEM);
    cudaFuncSetAttribute(attn_h,          cudaFuncAttributeMaxDynamicSharedMemorySize, ATT_SMEM);

    // merged weight conversion (single launch)
    convall_kernel<<<12288, 256>>>(Wq, Wk, Wv, Wo, Wup, Wdn,
                                   hwq, hwk, hwv, hwo, hwup, hwdn);

    dim3 gproj(DMODEL/128, MROWS/128);      // (8, 32)
    dim3 gqkv (DMODEL/128, MROWS/128, 3);
    dim3 gup  (DFF/128,    MROWS/128);      // (32, 32)

    // LN1 -> fp16
    ln_h_kernel<<<MROWS, 256>>>(x, ln1m, ln1s, hln1);
    // fused QKV -> half (Q pre-scaled by 1/8)
    gemmh_qkv<<<gqkv, 256, GH_SMEM>>>(hln1, hwq, hwk, hwv, hq, hk, hv);
    // fp16 flash attention -> half O (128 q-rows per CTA)
    attn_h<<<dim3(SEQ/128, NH, BDIM), 256, ATT_SMEM>>>(hq, hk, hv, hO);
    // out proj + residual -> y1 (fp32)
    gemmh<EPI_ADD><<<gproj, 256, GH_SMEM>>>(hO, hwo, x, b4, nullptr, DMODEL, DMODEL, 1.0f);
    // LN2 -> fp16
    ln_h_kernel<<<MROWS, 256>>>(b4, ln2m, ln2s, hln2);
    // MLP up + GELU -> half mid
    gemmh<EPI_GELU><<<gup, 256, GH_SMEM>>>(hln2, hwup, nullptr, nullptr, hmid, DFF, DMODEL, 1.0f);
    // MLP down + residual -> out (fp32)
    gemmh<EPI_ADD><<<gproj, 256, GH_SMEM>>>(hmid, hwdn, b4, out, nullptr, DMODEL, DFF, 1.0f);
}